// round 2
// baseline (speedup 1.0000x reference)
#include <cuda_runtime.h>
#include <math.h>

// Problem constants (fixed shapes per reference)
#define N_ROWS 2048
#define D_DIM  192
#define C_CLS  100000
#define S_SCALE 30.0f
#define MARGIN  0.2f

#define TN_TILE 64
#define NCHUNK ((C_CLS + TN_TILE - 1) / TN_TILE)   // 1563

// Scratch (device globals — allocation-free per harness rules)
__device__ __align__(16) float g_xn[N_ROWS * D_DIM];
__device__ float g_tgt[N_ROWS];
__device__ float g_pmax[(size_t)N_ROWS * NCHUNK];
__device__ float g_psum[(size_t)N_ROWS * NCHUNK];
__device__ float g_L[N_ROWS];
__device__ int   g_lab32;   // 1 if labels are int32, 0 if int64

// ---------------------------------------------------------------------------
// Kernel 0: detect label dtype touching ONLY the first 8 KB of the buffer
// (safe whether it's 2048 int32 or 2048 int64). If int64, odd int32 words
// (high halves of labels 0..1023) are all zero; if int32 they're random
// labels, virtually never all zero.
// ---------------------------------------------------------------------------
__global__ void detect_label_kernel(const int* __restrict__ lab) {
    __shared__ int any;
    if (threadIdx.x == 0) any = 0;
    __syncthreads();
    int v = 0;
    for (int i = threadIdx.x; i < 1024; i += blockDim.x)
        v |= lab[2 * i + 1];
    if (v) atomicOr(&any, 1);
    __syncthreads();
    if (threadIdx.x == 0) g_lab32 = (any != 0) ? 1 : 0;
}

// ---------------------------------------------------------------------------
// Kernel 1: per-row L2-normalize x -> g_xn, and target logit via gathered W row.
// One warp per row. D=192 = 6 * 32.
// ---------------------------------------------------------------------------
__global__ void norm_tgt_kernel(const float* __restrict__ x,
                                const float* __restrict__ W,
                                const void* __restrict__ label) {
    int warp = (blockIdx.x * blockDim.x + threadIdx.x) >> 5;
    int lane = threadIdx.x & 31;
    if (warp >= N_ROWS) return;

    const float* xr = x + (size_t)warp * D_DIM;
    float xv[6];
    float ss = 0.f;
#pragma unroll
    for (int j = 0; j < 6; j++) {
        xv[j] = xr[lane + 32 * j];
        ss += xv[j] * xv[j];
    }
#pragma unroll
    for (int o = 16; o; o >>= 1) ss += __shfl_xor_sync(0xffffffffu, ss, o);
    float inv = rsqrtf(ss);

    long long li = g_lab32 ? (long long)((const int*)label)[warp]
                           : ((const long long*)label)[warp];
    if (li < 0) li = 0;
    if (li >= C_CLS) li = C_CLS - 1;

    const float* wr = W + (size_t)li * D_DIM;
    float dot = 0.f;
#pragma unroll
    for (int j = 0; j < 6; j++) {
        g_xn[(size_t)warp * D_DIM + lane + 32 * j] = xv[j] * inv;
        dot += xv[j] * wr[lane + 32 * j];
    }
#pragma unroll
    for (int o = 16; o; o >>= 1) dot += __shfl_xor_sync(0xffffffffu, dot, o);
    if (lane == 0) g_tgt[warp] = dot * inv;
}

// ---------------------------------------------------------------------------
// Kernel 2: fused 64x64 GEMM tile (K=192) + per-row (max, sumexp) over the
// 64-class chunk. Partials -> g_pmax / g_psum.
// Thread layout: 16x16 (tx = class group, ty = row group), 4x4 reg tile.
// smem tiles stored K-major; row stride 68 floats = 272 B (16B multiple) so
// float4 LDS stays aligned.
// ---------------------------------------------------------------------------
__global__ void __launch_bounds__(256) gemm_lse_kernel(const float* __restrict__ W) {
    __shared__ float As[32][68];
    __shared__ float Bs[32][68];

    int tid = threadIdx.x;
    int tx = tid & 15;
    int ty = tid >> 4;
    int chunk   = blockIdx.x;
    int rowBase = blockIdx.y * 64;
    int colBase = chunk * 64;

    float acc[4][4] = {};

    for (int kk = 0; kk < D_DIM; kk += 32) {
        // cooperative load: 64 rows x 32 k per tile; 2 float4 per thread per tile
#pragma unroll
        for (int l = 0; l < 2; l++) {
            int id = tid + l * 256;
            int r  = id >> 3;            // 0..63
            int c4 = (id & 7) * 4;       // 0,4,...,28

            float4 a = *(const float4*)&g_xn[(size_t)(rowBase + r) * D_DIM + kk + c4];
            As[c4 + 0][r] = a.x; As[c4 + 1][r] = a.y;
            As[c4 + 2][r] = a.z; As[c4 + 3][r] = a.w;

            int col = colBase + r;
            float4 b = make_float4(0.f, 0.f, 0.f, 0.f);
            if (col < C_CLS)
                b = *(const float4*)&W[(size_t)col * D_DIM + kk + c4];
            Bs[c4 + 0][r] = b.x; Bs[c4 + 1][r] = b.y;
            Bs[c4 + 2][r] = b.z; Bs[c4 + 3][r] = b.w;
        }
        __syncthreads();

#pragma unroll
        for (int k = 0; k < 32; k++) {
            float4 a = *(const float4*)&As[k][ty * 4];
            float4 b = *(const float4*)&Bs[k][tx * 4];
            acc[0][0] += a.x * b.x; acc[0][1] += a.x * b.y; acc[0][2] += a.x * b.z; acc[0][3] += a.x * b.w;
            acc[1][0] += a.y * b.x; acc[1][1] += a.y * b.y; acc[1][2] += a.y * b.z; acc[1][3] += a.y * b.w;
            acc[2][0] += a.z * b.x; acc[2][1] += a.z * b.y; acc[2][2] += a.z * b.z; acc[2][3] += a.z * b.w;
            acc[3][0] += a.w * b.x; acc[3][1] += a.w * b.y; acc[3][2] += a.w * b.z; acc[3][3] += a.w * b.w;
        }
        __syncthreads();
    }

    // Epilogue: per row, reduce (max, sumexp) of S*logit across the 64 cols.
    // 16 tx-lanes per row group live in one half-warp: xor shuffles 8,4,2,1
    // stay inside the group.
#pragma unroll
    for (int i = 0; i < 4; i++) {
        float v[4];
        float m = -1e30f;
#pragma unroll
        for (int j = 0; j < 4; j++) {
            int c = colBase + tx * 4 + j;
            v[j] = (c < C_CLS) ? S_SCALE * acc[i][j] : -1e30f;
            m = fmaxf(m, v[j]);
        }
#pragma unroll
        for (int o = 8; o; o >>= 1) m = fmaxf(m, __shfl_xor_sync(0xffffffffu, m, o));
        float s = 0.f;
#pragma unroll
        for (int j = 0; j < 4; j++) s += __expf(v[j] - m);
#pragma unroll
        for (int o = 8; o; o >>= 1) s += __shfl_xor_sync(0xffffffffu, s, o);

        if (tx == 0) {
            int row = rowBase + ty * 4 + i;
            g_pmax[(size_t)row * NCHUNK + chunk] = m;
            g_psum[(size_t)row * NCHUNK + chunk] = s;
        }
    }
}

// ---------------------------------------------------------------------------
// Kernel 3: per-row combine of NCHUNK (m,s) partials + margin correction.
// Deterministic fixed-order tree reduction.
// ---------------------------------------------------------------------------
__global__ void combine_kernel() {
    int row = blockIdx.x;
    int t = threadIdx.x;

    float m = -1e30f, s = 0.f;
    const float* pm = g_pmax + (size_t)row * NCHUNK;
    const float* ps = g_psum + (size_t)row * NCHUNK;
    for (int c = t; c < NCHUNK; c += 256) {
        float cm = pm[c], cs = ps[c];
        if (cm > m) { s = s * __expf(m - cm) + cs; m = cm; }
        else        { s += cs * __expf(cm - m); }
    }

    __shared__ float sm[256];
    __shared__ float ssh[256];
    sm[t] = m; ssh[t] = s;
    __syncthreads();
    for (int st = 128; st > 0; st >>= 1) {
        if (t < st) {
            float ma = sm[t],  sa = ssh[t];
            float mb = sm[t + st], sb = ssh[t + st];
            if (mb > ma) { sm[t] = mb; ssh[t] = sb + sa * __expf(ma - mb); }
            else         {             ssh[t] = sa + sb * __expf(mb - ma); }
        }
        __syncthreads();
    }

    if (t == 0) {
        float mt = sm[0], stot = ssh[0];
        float tgt   = g_tgt[row];
        float numer = S_SCALE * (tgt - MARGIN);
        // replace label column: drop exp(S*tgt), add exp(numer). numer < S*tgt <= mt.
        float scorr = stot - __expf(S_SCALE * tgt - mt) + __expf(numer - mt);
        float lse = mt + logf(scorr);
        g_L[row] = numer - lse;
    }
}

// ---------------------------------------------------------------------------
// Kernel 4: deterministic 2048 -> 1 mean reduction.
// ---------------------------------------------------------------------------
__global__ void final_kernel(float* __restrict__ out) {
    __shared__ float sm[1024];
    int t = threadIdx.x;
    sm[t] = g_L[t] + g_L[t + 1024];
    __syncthreads();
    for (int st = 512; st > 0; st >>= 1) {
        if (t < st) sm[t] += sm[t + st];
        __syncthreads();
    }
    if (t == 0) out[0] = -sm[0] / (float)N_ROWS;
}

// ---------------------------------------------------------------------------
extern "C" void kernel_launch(void* const* d_in, const int* in_sizes, int n_in,
                              void* d_out, int out_size) {
    (void)in_sizes; (void)n_in; (void)out_size;
    const float* x     = (const float*)d_in[0];
    const float* W     = (const float*)d_in[1];
    const void*  label = d_in[2];
    float* out = (float*)d_out;

    detect_label_kernel<<<1, 256>>>((const int*)label);

    // 2048 rows, 8 warps per block -> 256 blocks
    norm_tgt_kernel<<<N_ROWS / 8, 256>>>(x, W, label);

    dim3 grid(NCHUNK, N_ROWS / 64);
    gemm_lse_kernel<<<grid, 256>>>(W);

    combine_kernel<<<N_ROWS, 256>>>();
    final_kernel<<<1, 1024>>>(out);
}

// round 4
// speedup vs baseline: 2.7405x; 2.7405x over previous
#include <cuda_runtime.h>
#include <math.h>
#include <stdint.h>

// Problem constants
#define N_ROWS 2048
#define D_DIM  192
#define C_CLS  100000
#define S_SCALE 30.0f
#define MARGIN  0.2f

#define NT 782            // 782*128 = 100096 >= 100000 class tiles
#define STRIPES 37        // grid (37,16) = 592 CTAs
#define A_STRIDE 196      // floats; (196*r + k) % 32 == (4r + k) % 32 -> conflict-free
#define B_STRIDE 36       // floats; (36*c + k) % 32 == (4c + k) % 32 -> conflict-free
#define A_FLOATS (128 * A_STRIDE)            // 25088
#define B_FLOATS (128 * B_STRIDE)            // 4608 per buffer
#define SMEM_TOTAL ((A_FLOATS + 2 * B_FLOATS) * 4)   // 137216 B

// ---------------- scratch globals ----------------
__device__ __align__(16) float g_xn[N_ROWS * D_DIM];
__device__ float g_tgt[N_ROWS];
__device__ float g_psum[(size_t)4 * NT * N_ROWS];   // [(ct*4 + wn)][row]
__device__ float g_L[N_ROWS];
__device__ int   g_lab32;

// ---------------- helpers (sm_80-level PTX only) ----------------
__device__ __forceinline__ uint32_t smem_u32(const void* p) {
    uint32_t a;
    asm("{ .reg .u64 t; cvta.to.shared.u64 t, %1; cvt.u32.u64 %0, t; }" : "=r"(a) : "l"(p));
    return a;
}
__device__ __forceinline__ void cp16(uint32_t dst, const void* src) {
    asm volatile("cp.async.cg.shared.global [%0], [%1], 16;" :: "r"(dst), "l"(src) : "memory");
}
#define CP_COMMIT() asm volatile("cp.async.commit_group;" ::: "memory")
#define CP_WAIT(n)  asm volatile("cp.async.wait_group %0;" :: "n"(n) : "memory")

__device__ __forceinline__ void mma8(float* c, uint32_t a0, uint32_t a1, uint32_t a2, uint32_t a3,
                                     uint32_t b0, uint32_t b1) {
    asm volatile(
        "mma.sync.aligned.m16n8k8.row.col.f32.tf32.tf32.f32 "
        "{%0,%1,%2,%3}, {%4,%5,%6,%7}, {%8,%9}, {%0,%1,%2,%3};"
        : "+f"(c[0]), "+f"(c[1]), "+f"(c[2]), "+f"(c[3])
        : "r"(a0), "r"(a1), "r"(a2), "r"(a3), "r"(b0), "r"(b1));
}

// exp(S*d) via exp2 range reduction + degree-5 poly. FFMA-only, |S*d| <= ~30.
__device__ __forceinline__ float exp_s(float d) {
    const float C = 43.2808512266689f;       // S * log2(e)
    const float MAGIC = 12582912.0f;         // 1.5 * 2^23
    float t = fmaf(d, C, MAGIC);
    float f = fmaf(d, C, MAGIC - t);         // y - n, one rounding
    int nb = __float_as_int(t);              // 0x4B400000 + n
    float p = fmaf(f, 0.0013333558f, 0.0096181291f);
    p = fmaf(f, p, 0.055504109f);
    p = fmaf(f, p, 0.24022651f);
    p = fmaf(f, p, 0.69314718f);
    p = fmaf(f, p, 1.0f);
    float sc = __int_as_float((nb << 23) + 0x3f800000);
    return p * sc;
}

// ---------------------------------------------------------------------------
// Kernel 0: label dtype detect (touches only first 8KB; safe either way)
// ---------------------------------------------------------------------------
__global__ void detect_label_kernel(const int* __restrict__ lab) {
    __shared__ int any;
    if (threadIdx.x == 0) any = 0;
    __syncthreads();
    int v = 0;
    for (int i = threadIdx.x; i < 1024; i += blockDim.x) v |= lab[2 * i + 1];
    if (v) atomicOr(&any, 1);
    __syncthreads();
    if (threadIdx.x == 0) g_lab32 = (any != 0) ? 1 : 0;
}

// ---------------------------------------------------------------------------
// Kernel 1: row normalize + exact target logit (fp32)
// ---------------------------------------------------------------------------
__global__ void norm_tgt_kernel(const float* __restrict__ x,
                                const float* __restrict__ W,
                                const void* __restrict__ label) {
    int warp = (blockIdx.x * blockDim.x + threadIdx.x) >> 5;
    int lane = threadIdx.x & 31;
    if (warp >= N_ROWS) return;

    const float* xr = x + (size_t)warp * D_DIM;
    float xv[6], ss = 0.f;
#pragma unroll
    for (int j = 0; j < 6; j++) { xv[j] = xr[lane + 32 * j]; ss += xv[j] * xv[j]; }
#pragma unroll
    for (int o = 16; o; o >>= 1) ss += __shfl_xor_sync(0xffffffffu, ss, o);
    float inv = rsqrtf(ss);

    long long li = g_lab32 ? (long long)((const int*)label)[warp]
                           : ((const long long*)label)[warp];
    if (li < 0) li = 0;
    if (li >= C_CLS) li = C_CLS - 1;

    const float* wr = W + (size_t)li * D_DIM;
    float dot = 0.f;
#pragma unroll
    for (int j = 0; j < 6; j++) {
        g_xn[(size_t)warp * D_DIM + lane + 32 * j] = xv[j] * inv;
        dot += xv[j] * wr[lane + 32 * j];
    }
#pragma unroll
    for (int o = 16; o; o >>= 1) dot += __shfl_xor_sync(0xffffffffu, dot, o);
    if (lane == 0) g_tgt[warp] = dot * inv;
}

// ---------------------------------------------------------------------------
// Kernel 2: tf32 mma.sync GEMM (128 rows x 128 classes per tile, K=192)
// fused with sum-exp epilogue. Persistent column stripes, double-buffered B.
//   warp grid 2(m) x 4(n); warp tile 64x32; 4x4 m16n8k8 fragments.
// ---------------------------------------------------------------------------
__global__ void __launch_bounds__(256, 1) gemm_lse_mma(const float* __restrict__ W) {
    extern __shared__ float smem[];
    float* As = smem;                    // [128][A_STRIDE]
    float* Bs = smem + A_FLOATS;         // 2 x [128][B_STRIDE]

    const int tid  = threadIdx.x;
    const int wid  = tid >> 5;
    const int lane = tid & 31;
    const int wm = wid >> 2, wn = wid & 3;
    const int qid = lane >> 2, qt = lane & 3;
    const int rowBase = blockIdx.y * 128;

    // ---- stage A (this CTA's 128 rows, full K) once ----
    for (int i = tid; i < 128 * 48; i += 256) {
        int r = i / 48, q = i % 48;
        cp16(smem_u32(As + r * A_STRIDE + q * 4),
             g_xn + (size_t)(rowBase + r) * D_DIM + q * 4);
    }
    CP_COMMIT();

    // B chunk loader: chunk c (32 k) of tile ct into buffer buf
    auto loadB = [&](int ct, int c, int buf) {
        float* bs = Bs + buf * B_FLOATS;
        int clsBase = ct * 128;
#pragma unroll
        for (int it = 0; it < 4; it++) {
            int i = tid + it * 256;          // 1024 16B chunks
            int r = i >> 3, q = i & 7;
            int cls = clsBase + r;
            if (cls >= C_CLS) cls = C_CLS - 1;   // clamp: stay in-bounds, values unused
            cp16(smem_u32(bs + r * B_STRIDE + q * 4),
                 W + (size_t)cls * D_DIM + c * 32 + q * 4);
        }
        CP_COMMIT();
    };

    CP_WAIT(0);          // A resident
    __syncthreads();

    const int ct0 = blockIdx.x;
    loadB(ct0, 0, 0);    // prefetch first chunk

    int g = 0;           // global chunk counter -> buffer parity
    for (int ct = ct0; ct < NT; ct += STRIPES) {
        float acc[4][4][4] = {};

        for (int c = 0; c < 6; c++, g++) {
            bool pre = true;
            if (c < 5)                    loadB(ct, c + 1, (g + 1) & 1);
            else if (ct + STRIPES < NT)   loadB(ct + STRIPES, 0, (g + 1) & 1);
            else                          pre = false;
            if (pre) { CP_WAIT(1); } else { CP_WAIT(0); }
            __syncthreads();

            const float* bs = Bs + (g & 1) * B_FLOATS;
#pragma unroll
            for (int ks = 0; ks < 4; ks++) {
                const int lk = ks * 8;
                uint32_t a[4][4];
#pragma unroll
                for (int mt = 0; mt < 4; mt++) {
                    const float* ap = As + (wm * 64 + mt * 16 + qid) * A_STRIDE + c * 32 + lk + qt;
                    a[mt][0] = __float_as_uint(ap[0]);
                    a[mt][1] = __float_as_uint(ap[8 * A_STRIDE]);
                    a[mt][2] = __float_as_uint(ap[4]);
                    a[mt][3] = __float_as_uint(ap[8 * A_STRIDE + 4]);
                }
#pragma unroll
                for (int nt = 0; nt < 4; nt++) {
                    const float* bp = bs + (wn * 32 + nt * 8 + qid) * B_STRIDE + lk + qt;
                    uint32_t b0 = __float_as_uint(bp[0]);
                    uint32_t b1 = __float_as_uint(bp[4]);
#pragma unroll
                    for (int mt = 0; mt < 4; mt++)
                        mma8(acc[mt][nt], a[mt][0], a[mt][1], a[mt][2], a[mt][3], b0, b1);
                }
            }
            __syncthreads();   // protect buffer (g&1) before it is refilled at g+2
        }

        // ---- epilogue: per-row sum of exp(S * logit) over this 128-col tile ----
        const bool tail = (ct == NT - 1);
#pragma unroll
        for (int mt = 0; mt < 4; mt++) {
            float sLo = 0.f, sHi = 0.f;
#pragma unroll
            for (int nt = 0; nt < 4; nt++) {
                int cls0 = ct * 128 + wn * 32 + nt * 8 + 2 * qt;
                bool v0 = !tail || (cls0     < C_CLS);
                bool v1 = !tail || (cls0 + 1 < C_CLS);
                if (v0) { sLo += exp_s(acc[mt][nt][0]); sHi += exp_s(acc[mt][nt][2]); }
                if (v1) { sLo += exp_s(acc[mt][nt][1]); sHi += exp_s(acc[mt][nt][3]); }
            }
            sLo += __shfl_xor_sync(0xffffffffu, sLo, 1);
            sLo += __shfl_xor_sync(0xffffffffu, sLo, 2);
            sHi += __shfl_xor_sync(0xffffffffu, sHi, 1);
            sHi += __shfl_xor_sync(0xffffffffu, sHi, 2);
            if (qt == 0) {
                int row = rowBase + wm * 64 + mt * 16 + qid;
                size_t base = ((size_t)ct * 4 + wn) * N_ROWS;
                g_psum[base + row]     = sLo;
                g_psum[base + row + 8] = sHi;
            }
        }
    }
}

// ---------------------------------------------------------------------------
// Kernel 3: per-row total + margin correction (|logit| <= ~30, no max shift)
// ---------------------------------------------------------------------------
__global__ void combine_kernel() {
    int row = blockIdx.x * blockDim.x + threadIdx.x;
    if (row >= N_ROWS) return;
    float s0 = 0.f, s1 = 0.f, s2 = 0.f, s3 = 0.f;
    const float* p = g_psum;
    for (int c = 0; c + 4 <= 4 * NT; c += 4) {
        s0 += p[(size_t)(c + 0) * N_ROWS + row];
        s1 += p[(size_t)(c + 1) * N_ROWS + row];
        s2 += p[(size_t)(c + 2) * N_ROWS + row];
        s3 += p[(size_t)(c + 3) * N_ROWS + row];
    }
    float s = (s0 + s1) + (s2 + s3);
    float tgt   = g_tgt[row];
    float numer = S_SCALE * (tgt - MARGIN);
    float scorr = s - expf(S_SCALE * tgt) + expf(numer);
    g_L[row] = numer - logf(scorr);
}

// ---------------------------------------------------------------------------
// Kernel 4: mean
// ---------------------------------------------------------------------------
__global__ void final_kernel(float* __restrict__ out) {
    __shared__ float sm[1024];
    int t = threadIdx.x;
    sm[t] = g_L[t] + g_L[t + 1024];
    __syncthreads();
    for (int st = 512; st > 0; st >>= 1) {
        if (t < st) sm[t] += sm[t + st];
        __syncthreads();
    }
    if (t == 0) out[0] = -sm[0] / (float)N_ROWS;
}

// ---------------------------------------------------------------------------
extern "C" void kernel_launch(void* const* d_in, const int* in_sizes, int n_in,
                              void* d_out, int out_size) {
    (void)in_sizes; (void)n_in; (void)out_size;
    const float* x     = (const float*)d_in[0];
    const float* W     = (const float*)d_in[1];
    const void*  label = d_in[2];
    float* out = (float*)d_out;

    cudaFuncSetAttribute(gemm_lse_mma, cudaFuncAttributeMaxDynamicSharedMemorySize, SMEM_TOTAL);

    detect_label_kernel<<<1, 256>>>((const int*)label);
    norm_tgt_kernel<<<N_ROWS / 8, 256>>>(x, W, label);

    dim3 grid(STRIPES, N_ROWS / 128);
    gemm_lse_mma<<<grid, 256, SMEM_TOTAL>>>(W);

    combine_kernel<<<N_ROWS / 256, 256>>>();
    final_kernel<<<1, 1024>>>(out);
}

// round 5
// speedup vs baseline: 4.1637x; 1.5193x over previous
#include <cuda_runtime.h>
#include <math.h>
#include <stdint.h>

// Problem constants
#define N_ROWS 2048
#define D_DIM  192
#define C_CLS  100000
#define S_SCALE 30.0f
#define MARGIN  0.2f

#define NT 782            // 782*128 = 100096 >= 100000 class tiles
#define STRIPES 37        // grid (37,16) = 592 CTAs = 4 clean waves
#define NPART (STRIPES * 4)   // 148 partials per row
#define B_STRIDE 36       // floats; (36*c + k) % 32 == (4c + k) % 32 -> conflict-free
#define A_FLOATS (192 * 32 * 4)              // 24576 floats (192 frags x 32 lanes x float4)
#define B_FLOATS (128 * B_STRIDE)            // 4608 per buffer
#define SMEM_TOTAL ((A_FLOATS + 2 * B_FLOATS) * 4)   // 135168 B

// ---------------- scratch globals ----------------
__device__ __align__(16) float g_xn[N_ROWS * D_DIM];
__device__ float g_tgt[N_ROWS];
__device__ float g_psum[(size_t)N_ROWS * NPART];   // [row][stripe*4+wn]
__device__ float g_L[N_ROWS];
__device__ int   g_lab32;

// ---------------- helpers (sm_80-level PTX only) ----------------
__device__ __forceinline__ uint32_t smem_u32(const void* p) {
    uint32_t a;
    asm("{ .reg .u64 t; cvta.to.shared.u64 t, %1; cvt.u32.u64 %0, t; }" : "=r"(a) : "l"(p));
    return a;
}
__device__ __forceinline__ void cp16(uint32_t dst, const void* src) {
    asm volatile("cp.async.cg.shared.global [%0], [%1], 16;" :: "r"(dst), "l"(src) : "memory");
}
#define CP_COMMIT() asm volatile("cp.async.commit_group;" ::: "memory")
#define CP_WAIT(n)  asm volatile("cp.async.wait_group %0;" :: "n"(n) : "memory")

__device__ __forceinline__ void mma8(float* c, uint32_t a0, uint32_t a1, uint32_t a2, uint32_t a3,
                                     uint32_t b0, uint32_t b1) {
    asm volatile(
        "mma.sync.aligned.m16n8k8.row.col.f32.tf32.tf32.f32 "
        "{%0,%1,%2,%3}, {%4,%5,%6,%7}, {%8,%9}, {%0,%1,%2,%3};"
        : "+f"(c[0]), "+f"(c[1]), "+f"(c[2]), "+f"(c[3])
        : "r"(a0), "r"(a1), "r"(a2), "r"(a3), "r"(b0), "r"(b1));
}

// exp(S*d) via exp2 range reduction + degree-5 poly. FFMA-only, |S*d| <= ~30.
__device__ __forceinline__ float exp_s(float d) {
    const float C = 43.2808512266689f;       // S * log2(e)
    const float MAGIC = 12582912.0f;         // 1.5 * 2^23
    float t = fmaf(d, C, MAGIC);
    float f = fmaf(d, C, MAGIC - t);         // y - n, one rounding
    int nb = __float_as_int(t);              // 0x4B400000 + n
    float p = fmaf(f, 0.0013333558f, 0.0096181291f);
    p = fmaf(f, p, 0.055504109f);
    p = fmaf(f, p, 0.24022651f);
    p = fmaf(f, p, 0.69314718f);
    p = fmaf(f, p, 1.0f);
    float sc = __int_as_float((nb << 23) + 0x3f800000);
    return p * sc;
}

// ---------------------------------------------------------------------------
// Kernel 0: label dtype detect (touches only first 8KB; safe either way)
// ---------------------------------------------------------------------------
__global__ void detect_label_kernel(const int* __restrict__ lab) {
    __shared__ int any;
    if (threadIdx.x == 0) any = 0;
    __syncthreads();
    int v = 0;
    for (int i = threadIdx.x; i < 1024; i += blockDim.x) v |= lab[2 * i + 1];
    if (v) atomicOr(&any, 1);
    __syncthreads();
    if (threadIdx.x == 0) g_lab32 = (any != 0) ? 1 : 0;
}

// ---------------------------------------------------------------------------
// Kernel 1: row normalize + exact target logit (fp32)
// ---------------------------------------------------------------------------
__global__ void norm_tgt_kernel(const float* __restrict__ x,
                                const float* __restrict__ W,
                                const void* __restrict__ label) {
    int warp = (blockIdx.x * blockDim.x + threadIdx.x) >> 5;
    int lane = threadIdx.x & 31;
    if (warp >= N_ROWS) return;

    const float* xr = x + (size_t)warp * D_DIM;
    float xv[6], ss = 0.f;
#pragma unroll
    for (int j = 0; j < 6; j++) { xv[j] = xr[lane + 32 * j]; ss += xv[j] * xv[j]; }
#pragma unroll
    for (int o = 16; o; o >>= 1) ss += __shfl_xor_sync(0xffffffffu, ss, o);
    float inv = rsqrtf(ss);

    long long li = g_lab32 ? (long long)((const int*)label)[warp]
                           : ((const long long*)label)[warp];
    if (li < 0) li = 0;
    if (li >= C_CLS) li = C_CLS - 1;

    const float* wr = W + (size_t)li * D_DIM;
    float dot = 0.f;
#pragma unroll
    for (int j = 0; j < 6; j++) {
        g_xn[(size_t)warp * D_DIM + lane + 32 * j] = xv[j] * inv;
        dot += xv[j] * wr[lane + 32 * j];
    }
#pragma unroll
    for (int o = 16; o; o >>= 1) dot += __shfl_xor_sync(0xffffffffu, dot, o);
    if (lane == 0) g_tgt[warp] = dot * inv;
}

// ---------------------------------------------------------------------------
// Kernel 2: tf32 mma.sync GEMM (128 rows x 128 classes per tile, K=192) fused
// with sum-exp epilogue. Persistent column stripes; double-buffered B via
// cp.async; A pre-permuted into fragment order (one LDS.128 per fragment);
// row-sums accumulate in registers across the whole stripe.
//   warp grid 2(m) x 4(n); warp tile 64x32; 4x4 m16n8k8 fragments.
// ---------------------------------------------------------------------------
__global__ void __launch_bounds__(256, 1) gemm_lse_mma(const float* __restrict__ W) {
    extern __shared__ float smem[];
    float4* As4 = (float4*)smem;          // [192 frags][32 lanes]
    float*  Bs  = smem + A_FLOATS;        // 2 x [128][B_STRIDE]

    const int tid  = threadIdx.x;
    const int wid  = tid >> 5;
    const int lane = tid & 31;
    const int wm = wid >> 2, wn = wid & 3;
    const int qid = lane >> 2, qt = lane & 3;
    const int rowBase = blockIdx.y * 128;

    // ---- stage A once, permuted into m16n8k8 A-fragment order ----
    // frag f = fm*24 + ks, fm = wm*4+mt (16-row group), ks = global k-step.
    for (int f = wid; f < 192; f += 8) {
        int fm = f / 24;
        int ks = f % 24;
        const float* base = g_xn + (size_t)(rowBase + fm * 16 + qid) * D_DIM + ks * 8 + qt;
        As4[f * 32 + lane] = make_float4(base[0], base[8 * D_DIM],
                                         base[4], base[8 * D_DIM + 4]);
    }

    // B chunk loader: chunk c (32 k) of tile ct into buffer buf
    auto loadB = [&](int ct, int c, int buf) {
        float* bs = Bs + buf * B_FLOATS;
        int clsBase = ct * 128;
#pragma unroll
        for (int it = 0; it < 4; it++) {
            int i = tid + it * 256;          // 1024 16B chunks
            int r = i >> 3, q = i & 7;
            int cls = clsBase + r;
            if (cls >= C_CLS) cls = C_CLS - 1;   // clamp: in-bounds, values unused
            cp16(smem_u32(bs + r * B_STRIDE + q * 4),
                 W + (size_t)cls * D_DIM + c * 32 + q * 4);
        }
        CP_COMMIT();
    };

    const int ct0 = blockIdx.x;
    loadB(ct0, 0, 0);    // prefetch first chunk
    CP_WAIT(0);
    __syncthreads();     // A staged + first B chunk resident

    float rsum[4][2] = {};   // per-thread running sum of exp over all stripe tiles

    int g = 0;               // global chunk counter -> buffer parity
    for (int ct = ct0; ct < NT; ct += STRIPES) {
        float acc[4][4][4] = {};

        for (int c = 0; c < 6; c++, g++) {
            bool pre = true;
            if (c < 5)                    loadB(ct, c + 1, (g + 1) & 1);
            else if (ct + STRIPES < NT)   loadB(ct + STRIPES, 0, (g + 1) & 1);
            else                          pre = false;
            if (pre) { CP_WAIT(1); } else { CP_WAIT(0); }
            __syncthreads();

            const float* bs = Bs + (g & 1) * B_FLOATS;
            const float4* af = As4 + (size_t)(wm * 4) * 24 * 32 + c * 4 * 32 + lane;
#pragma unroll
            for (int ks = 0; ks < 4; ks++) {
                float4 a[4];
#pragma unroll
                for (int mt = 0; mt < 4; mt++)
                    a[mt] = af[(mt * 24 + ks) * 32];
#pragma unroll
                for (int nt = 0; nt < 4; nt++) {
                    const float* bp = bs + (wn * 32 + nt * 8 + qid) * B_STRIDE + ks * 8 + qt;
                    uint32_t b0 = __float_as_uint(bp[0]);
                    uint32_t b1 = __float_as_uint(bp[4]);
#pragma unroll
                    for (int mt = 0; mt < 4; mt++)
                        mma8(acc[mt][nt],
                             __float_as_uint(a[mt].x), __float_as_uint(a[mt].y),
                             __float_as_uint(a[mt].z), __float_as_uint(a[mt].w),
                             b0, b1);
                }
            }
            __syncthreads();   // all reads of buf (g&1) done before refill at g+2
        }

        // ---- accumulate exp(S*logit) into register row-sums ----
        if (ct != NT - 1) {
#pragma unroll
            for (int mt = 0; mt < 4; mt++) {
#pragma unroll
                for (int nt = 0; nt < 4; nt++) {
                    rsum[mt][0] += exp_s(acc[mt][nt][0]) + exp_s(acc[mt][nt][1]);
                    rsum[mt][1] += exp_s(acc[mt][nt][2]) + exp_s(acc[mt][nt][3]);
                }
            }
        } else {
#pragma unroll
            for (int mt = 0; mt < 4; mt++) {
#pragma unroll
                for (int nt = 0; nt < 4; nt++) {
                    int cls0 = ct * 128 + wn * 32 + nt * 8 + 2 * qt;
                    if (cls0 < C_CLS)     { rsum[mt][0] += exp_s(acc[mt][nt][0]);
                                            rsum[mt][1] += exp_s(acc[mt][nt][2]); }
                    if (cls0 + 1 < C_CLS) { rsum[mt][0] += exp_s(acc[mt][nt][1]);
                                            rsum[mt][1] += exp_s(acc[mt][nt][3]); }
                }
            }
        }
    }

    // ---- one partial per (stripe, wn) per row ----
    const int cidx = blockIdx.x * 4 + wn;
#pragma unroll
    for (int mt = 0; mt < 4; mt++) {
        float sLo = rsum[mt][0], sHi = rsum[mt][1];
        sLo += __shfl_xor_sync(0xffffffffu, sLo, 1);
        sLo += __shfl_xor_sync(0xffffffffu, sLo, 2);
        sHi += __shfl_xor_sync(0xffffffffu, sHi, 1);
        sHi += __shfl_xor_sync(0xffffffffu, sHi, 2);
        if (qt == 0) {
            int row = rowBase + wm * 64 + mt * 16 + qid;
            g_psum[(size_t)row * NPART + cidx]       = sLo;
            g_psum[(size_t)(row + 8) * NPART + cidx] = sHi;
        }
    }
}

// ---------------------------------------------------------------------------
// Kernel 3: warp per row: sum 148 partials + margin correction
// ---------------------------------------------------------------------------
__global__ void combine_kernel() {
    int row  = blockIdx.x * 8 + (threadIdx.x >> 5);
    int lane = threadIdx.x & 31;
    const float* p = g_psum + (size_t)row * NPART;
    float s = 0.f;
    for (int c = lane; c < NPART; c += 32) s += p[c];
#pragma unroll
    for (int o = 16; o; o >>= 1) s += __shfl_xor_sync(0xffffffffu, s, o);
    if (lane == 0) {
        float tgt   = g_tgt[row];
        float numer = S_SCALE * (tgt - MARGIN);
        float scorr = s - expf(S_SCALE * tgt) + expf(numer);
        g_L[row] = numer - logf(scorr);
    }
}

// ---------------------------------------------------------------------------
// Kernel 4: mean
// ---------------------------------------------------------------------------
__global__ void final_kernel(float* __restrict__ out) {
    __shared__ float sm[1024];
    int t = threadIdx.x;
    sm[t] = g_L[t] + g_L[t + 1024];
    __syncthreads();
    for (int st = 512; st > 0; st >>= 1) {
        if (t < st) sm[t] += sm[t + st];
        __syncthreads();
    }
    if (t == 0) out[0] = -sm[0] / (float)N_ROWS;
}

// ---------------------------------------------------------------------------
extern "C" void kernel_launch(void* const* d_in, const int* in_sizes, int n_in,
                              void* d_out, int out_size) {
    (void)in_sizes; (void)n_in; (void)out_size;
    const float* x     = (const float*)d_in[0];
    const float* W     = (const float*)d_in[1];
    const void*  label = d_in[2];
    float* out = (float*)d_out;

    cudaFuncSetAttribute(gemm_lse_mma, cudaFuncAttributeMaxDynamicSharedMemorySize, SMEM_TOTAL);

    detect_label_kernel<<<1, 256>>>((const int*)label);
    norm_tgt_kernel<<<N_ROWS / 8, 256>>>(x, W, label);

    dim3 grid(STRIPES, N_ROWS / 128);
    gemm_lse_mma<<<grid, 256, SMEM_TOTAL>>>(W);

    combine_kernel<<<N_ROWS / 8, 256>>>();
    final_kernel<<<1, 1024>>>(out);
}

// round 6
// speedup vs baseline: 4.5026x; 1.0814x over previous
#include <cuda_runtime.h>
#include <math.h>
#include <stdint.h>

// Problem constants
#define N_ROWS 2048
#define D_DIM  192
#define C_CLS  100000
#define S_SCALE 30.0f
#define MARGIN  0.2f

#define NT256 391         // ceil(100000/256) class tiles of 256
#define STRIPES 37        // grid (37,16) = 592 CTAs = 4 clean waves
#define NPART (STRIPES * 4)   // 148 partials per row
#define B_STRIDE 36       // floats; conflict-free (bank = 4*cls + k mod 32)
#define B_CLS 256         // classes per tile
#define A_FLOATS (192 * 32 * 4)              // 24576 floats (192 frags x 32 lanes x float4)
#define B_FLOATS (B_CLS * B_STRIDE)          // 9216 floats per buffer
#define SMEM_TOTAL ((A_FLOATS + 3 * B_FLOATS) * 4)   // 208896 B

// ---------------- scratch globals ----------------
__device__ __align__(16) float g_xn[N_ROWS * D_DIM];
__device__ float g_tgt[N_ROWS];
__device__ float g_psum[(size_t)N_ROWS * NPART];   // [row][stripe*4+wn]
__device__ float g_L[N_ROWS];
__device__ int   g_lab32;

// ---------------- helpers (sm_80-level PTX only) ----------------
__device__ __forceinline__ uint32_t smem_u32(const void* p) {
    uint32_t a;
    asm("{ .reg .u64 t; cvta.to.shared.u64 t, %1; cvt.u32.u64 %0, t; }" : "=r"(a) : "l"(p));
    return a;
}
__device__ __forceinline__ void cp16(uint32_t dst, const void* src) {
    asm volatile("cp.async.cg.shared.global [%0], [%1], 16;" :: "r"(dst), "l"(src) : "memory");
}
#define CP_COMMIT() asm volatile("cp.async.commit_group;" ::: "memory")
#define CP_WAIT(n)  asm volatile("cp.async.wait_group %0;" :: "n"(n) : "memory")

__device__ __forceinline__ void mma8(float* c, uint32_t a0, uint32_t a1, uint32_t a2, uint32_t a3,
                                     uint32_t b0, uint32_t b1) {
    asm volatile(
        "mma.sync.aligned.m16n8k8.row.col.f32.tf32.tf32.f32 "
        "{%0,%1,%2,%3}, {%4,%5,%6,%7}, {%8,%9}, {%0,%1,%2,%3};"
        : "+f"(c[0]), "+f"(c[1]), "+f"(c[2]), "+f"(c[3])
        : "r"(a0), "r"(a1), "r"(a2), "r"(a3), "r"(b0), "r"(b1));
}

// exp(S*d) = 2^(S*log2(e)*d) via MUFU ex2 (1 FMUL + 1 MUFU, ~2^-22 rel err)
__device__ __forceinline__ float exp_s(float d) {
    float r;
    asm("ex2.approx.f32 %0, %1;" : "=f"(r) : "f"(43.2808512266689f * d));
    return r;
}

// ---------------------------------------------------------------------------
// Kernel 0: label dtype detect (touches only first 8KB; safe either way)
// ---------------------------------------------------------------------------
__global__ void detect_label_kernel(const int* __restrict__ lab) {
    __shared__ int any;
    if (threadIdx.x == 0) any = 0;
    __syncthreads();
    int v = 0;
    for (int i = threadIdx.x; i < 1024; i += blockDim.x) v |= lab[2 * i + 1];
    if (v) atomicOr(&any, 1);
    __syncthreads();
    if (threadIdx.x == 0) g_lab32 = (any != 0) ? 1 : 0;
}

// ---------------------------------------------------------------------------
// Kernel 1: row normalize + exact target logit (fp32)
// ---------------------------------------------------------------------------
__global__ void norm_tgt_kernel(const float* __restrict__ x,
                                const float* __restrict__ W,
                                const void* __restrict__ label) {
    int warp = (blockIdx.x * blockDim.x + threadIdx.x) >> 5;
    int lane = threadIdx.x & 31;
    if (warp >= N_ROWS) return;

    const float* xr = x + (size_t)warp * D_DIM;
    float xv[6], ss = 0.f;
#pragma unroll
    for (int j = 0; j < 6; j++) { xv[j] = xr[lane + 32 * j]; ss += xv[j] * xv[j]; }
#pragma unroll
    for (int o = 16; o; o >>= 1) ss += __shfl_xor_sync(0xffffffffu, ss, o);
    float inv = rsqrtf(ss);

    long long li = g_lab32 ? (long long)((const int*)label)[warp]
                           : ((const long long*)label)[warp];
    if (li < 0) li = 0;
    if (li >= C_CLS) li = C_CLS - 1;

    const float* wr = W + (size_t)li * D_DIM;
    float dot = 0.f;
#pragma unroll
    for (int j = 0; j < 6; j++) {
        g_xn[(size_t)warp * D_DIM + lane + 32 * j] = xv[j] * inv;
        dot += xv[j] * wr[lane + 32 * j];
    }
#pragma unroll
    for (int o = 16; o; o >>= 1) dot += __shfl_xor_sync(0xffffffffu, dot, o);
    if (lane == 0) g_tgt[warp] = dot * inv;
}

// ---------------------------------------------------------------------------
// Kernel 2: tf32 mma.sync GEMM, 128 rows x 256 classes per tile, K=192.
// 3-stage cp.async B pipeline, 1 barrier/chunk; A pre-permuted to fragment
// order (LDS.128); MUFU exp epilogue accumulated in registers per stripe.
//   warp grid 2(m) x 4(n); warp tile 64x64; 4(mt) x 8(nt) m16n8k8 fragments.
// ---------------------------------------------------------------------------
__global__ void __launch_bounds__(256, 1) gemm_lse_mma(const float* __restrict__ W) {
    extern __shared__ float smem[];
    float4* As4 = (float4*)smem;          // [192 frags][32 lanes]
    float*  Bs  = smem + A_FLOATS;        // 3 x [256][B_STRIDE]

    const int tid  = threadIdx.x;
    const int wid  = tid >> 5;
    const int lane = tid & 31;
    const int wm = wid >> 2, wn = wid & 3;
    const int qid = lane >> 2, qt = lane & 3;
    const int rowBase = blockIdx.y * 128;
    const int ct0 = blockIdx.x;

    // ---- stage A once, permuted into m16n8k8 A-fragment order ----
    for (int f = wid; f < 192; f += 8) {
        int fm = f / 24;                  // 16-row group
        int ks = f % 24;                  // global k-step
        const float* base = g_xn + (size_t)(rowBase + fm * 16 + qid) * D_DIM + ks * 8 + qt;
        As4[f * 32 + lane] = make_float4(base[0], base[8 * D_DIM],
                                         base[4], base[8 * D_DIM + 4]);
    }

    // B chunk loader: chunk c (32 k) of tile ct into buffer buf
    auto loadB = [&](int ct, int c, int buf) {
        float* bs = Bs + buf * B_FLOATS;
        int clsBase = ct * B_CLS;
#pragma unroll
        for (int it = 0; it < 8; it++) {
            int i = tid + it * 256;          // 2048 16B chunks
            int r = i >> 3, q = i & 7;
            int cls = clsBase + r;
            if (cls >= C_CLS) cls = C_CLS - 1;   // clamp: in-bounds, values unused
            cp16(smem_u32(bs + r * B_STRIDE + q * 4),
                 W + (size_t)cls * D_DIM + c * 32 + q * 4);
        }
        CP_COMMIT();
    };

    const int ntiles = (NT256 - 1 - ct0) / STRIPES + 1;
    const int total  = ntiles * 6;

    loadB(ct0, 0, 0);
    if (total > 1) loadB(ct0, 1, 1);

    float rsum[4][2] = {};
    float acc[4][8][4];

    for (int g = 0; g < total; ++g) {
        const int c  = g % 6;
        const int ti = g / 6;
        const int ct = ct0 + ti * STRIPES;

        if (g == total - 1) { CP_WAIT(0); } else { CP_WAIT(1); }
        __syncthreads();   // buffer g%3 visible to all; prior readers of (g+2)%3 done

        if (g + 2 < total) {
            int gn = g + 2;
            loadB(ct0 + (gn / 6) * STRIPES, gn % 6, gn % 3);
        }

        if (c == 0) {
#pragma unroll
            for (int mt = 0; mt < 4; mt++)
#pragma unroll
                for (int nt = 0; nt < 8; nt++)
#pragma unroll
                    for (int e = 0; e < 4; e++) acc[mt][nt][e] = 0.f;
        }

        const float* bs = Bs + (g % 3) * B_FLOATS;
        const float4* af = As4 + (size_t)(wm * 4) * 24 * 32 + c * 4 * 32 + lane;
#pragma unroll
        for (int ks = 0; ks < 4; ks++) {
            float4 a[4];
#pragma unroll
            for (int mt = 0; mt < 4; mt++)
                a[mt] = af[(mt * 24 + ks) * 32];
#pragma unroll
            for (int nt = 0; nt < 8; nt++) {
                const float* bp = bs + (wn * 64 + nt * 8 + qid) * B_STRIDE + ks * 8 + qt;
                uint32_t b0 = __float_as_uint(bp[0]);
                uint32_t b1 = __float_as_uint(bp[4]);
#pragma unroll
                for (int mt = 0; mt < 4; mt++)
                    mma8(acc[mt][nt],
                         __float_as_uint(a[mt].x), __float_as_uint(a[mt].y),
                         __float_as_uint(a[mt].z), __float_as_uint(a[mt].w),
                         b0, b1);
            }
        }

        if (c == 5) {
            // ---- accumulate exp(S*logit) into register row-sums ----
            if (ct != NT256 - 1) {
#pragma unroll
                for (int mt = 0; mt < 4; mt++)
#pragma unroll
                    for (int nt = 0; nt < 8; nt++) {
                        rsum[mt][0] += exp_s(acc[mt][nt][0]) + exp_s(acc[mt][nt][1]);
                        rsum[mt][1] += exp_s(acc[mt][nt][2]) + exp_s(acc[mt][nt][3]);
                    }
            } else {
#pragma unroll
                for (int mt = 0; mt < 4; mt++)
#pragma unroll
                    for (int nt = 0; nt < 8; nt++) {
                        int cls0 = ct * B_CLS + wn * 64 + nt * 8 + 2 * qt;
                        if (cls0 < C_CLS)     { rsum[mt][0] += exp_s(acc[mt][nt][0]);
                                                rsum[mt][1] += exp_s(acc[mt][nt][2]); }
                        if (cls0 + 1 < C_CLS) { rsum[mt][0] += exp_s(acc[mt][nt][1]);
                                                rsum[mt][1] += exp_s(acc[mt][nt][3]); }
                    }
            }
        }
    }

    // ---- one partial per (stripe, wn) per row ----
    const int cidx = blockIdx.x * 4 + wn;
#pragma unroll
    for (int mt = 0; mt < 4; mt++) {
        float sLo = rsum[mt][0], sHi = rsum[mt][1];
        sLo += __shfl_xor_sync(0xffffffffu, sLo, 1);
        sLo += __shfl_xor_sync(0xffffffffu, sLo, 2);
        sHi += __shfl_xor_sync(0xffffffffu, sHi, 1);
        sHi += __shfl_xor_sync(0xffffffffu, sHi, 2);
        if (qt == 0) {
            int row = rowBase + wm * 64 + mt * 16 + qid;
            g_psum[(size_t)row * NPART + cidx]       = sLo;
            g_psum[(size_t)(row + 8) * NPART + cidx] = sHi;
        }
    }
}

// ---------------------------------------------------------------------------
// Kernel 3: warp per row: sum 148 partials + margin correction
// ---------------------------------------------------------------------------
__global__ void combine_kernel() {
    int row  = blockIdx.x * 8 + (threadIdx.x >> 5);
    int lane = threadIdx.x & 31;
    const float* p = g_psum + (size_t)row * NPART;
    float s = 0.f;
    for (int c = lane; c < NPART; c += 32) s += p[c];
#pragma unroll
    for (int o = 16; o; o >>= 1) s += __shfl_xor_sync(0xffffffffu, s, o);
    if (lane == 0) {
        float tgt   = g_tgt[row];
        float numer = S_SCALE * (tgt - MARGIN);
        float scorr = s - expf(S_SCALE * tgt) + expf(numer);
        g_L[row] = numer - logf(scorr);
    }
}

// ---------------------------------------------------------------------------
// Kernel 4: mean
// ---------------------------------------------------------------------------
__global__ void final_kernel(float* __restrict__ out) {
    __shared__ float sm[1024];
    int t = threadIdx.x;
    sm[t] = g_L[t] + g_L[t + 1024];
    __syncthreads();
    for (int st = 512; st > 0; st >>= 1) {
        if (t < st) sm[t] += sm[t + st];
        __syncthreads();
    }
    if (t == 0) out[0] = -sm[0] / (float)N_ROWS;
}

// ---------------------------------------------------------------------------
extern "C" void kernel_launch(void* const* d_in, const int* in_sizes, int n_in,
                              void* d_out, int out_size) {
    (void)in_sizes; (void)n_in; (void)out_size;
    const float* x     = (const float*)d_in[0];
    const float* W     = (const float*)d_in[1];
    const void*  label = d_in[2];
    float* out = (float*)d_out;

    cudaFuncSetAttribute(gemm_lse_mma, cudaFuncAttributeMaxDynamicSharedMemorySize, SMEM_TOTAL);

    detect_label_kernel<<<1, 256>>>((const int*)label);
    norm_tgt_kernel<<<N_ROWS / 8, 256>>>(x, W, label);

    dim3 grid(STRIPES, N_ROWS / 128);
    gemm_lse_mma<<<grid, 256, SMEM_TOTAL>>>(W);

    combine_kernel<<<N_ROWS / 8, 256>>>();
    final_kernel<<<1, 1024>>>(out);
}

// round 7
// speedup vs baseline: 6.4393x; 1.4301x over previous
#include <cuda_runtime.h>
#include <math.h>
#include <stdint.h>

// Problem constants
#define N_ROWS 2048
#define D_DIM  192
#define C_CLS  100000
#define S_SCALE 30.0f
#define MARGIN  0.2f

#define NT256 391         // ceil(100000/256) class tiles of 256
#define CPAD  100096      // NT256*256, padded class count
#define STRIPES 37        // grid (37,16) = 592 CTAs = 4 clean waves
#define NPART (STRIPES * 4)   // 148 partials per row
#define B_STRIDE_W 20     // words per class row (16 data + 4 pad) -> conflict-free
#define B_CLS 256
#define A_WORDS (96 * 32 * 4)                 // 96 frags x 32 lanes x uint4
#define B_WORDS (B_CLS * B_STRIDE_W)          // 5120 words per stage
#define SMEM_TOTAL ((A_WORDS + 3 * B_WORDS) * 4)   // 110592 B

// ---------------- scratch globals ----------------
__device__ __align__(16) float g_xn[N_ROWS * D_DIM];
__device__ __align__(16) unsigned short g_wbf[(size_t)CPAD * D_DIM];  // bf16, k-pair permuted
__device__ float g_tgt[N_ROWS];
__device__ float g_psum[(size_t)N_ROWS * NPART];
__device__ float g_L[N_ROWS];
__device__ int   g_lab32;

// ---------------- helpers (sm_80-level PTX only) ----------------
__device__ __forceinline__ uint32_t smem_u32(const void* p) {
    uint32_t a;
    asm("{ .reg .u64 t; cvta.to.shared.u64 t, %1; cvt.u32.u64 %0, t; }" : "=r"(a) : "l"(p));
    return a;
}
__device__ __forceinline__ void cp16(uint32_t dst, const void* src) {
    asm volatile("cp.async.cg.shared.global [%0], [%1], 16;" :: "r"(dst), "l"(src) : "memory");
}
#define CP_COMMIT() asm volatile("cp.async.commit_group;" ::: "memory")
#define CP_WAIT(n)  asm volatile("cp.async.wait_group %0;" :: "n"(n) : "memory")

// pack(lo, hi): bf16x2 register {hi:lo}
__device__ __forceinline__ uint32_t bfpack(float lo, float hi) {
    uint32_t r;
    asm("cvt.rn.bf16x2.f32 %0, %1, %2;" : "=r"(r) : "f"(hi), "f"(lo));
    return r;
}

__device__ __forceinline__ void mma16(float* c, const uint32_t* a, uint32_t b0, uint32_t b1) {
    asm volatile(
        "mma.sync.aligned.m16n8k16.row.col.f32.bf16.bf16.f32 "
        "{%0,%1,%2,%3}, {%4,%5,%6,%7}, {%8,%9}, {%0,%1,%2,%3};"
        : "+f"(c[0]), "+f"(c[1]), "+f"(c[2]), "+f"(c[3])
        : "r"(a[0]), "r"(a[1]), "r"(a[2]), "r"(a[3]), "r"(b0), "r"(b1));
}

// exp(S*d) = 2^(S*log2(e)*d) via MUFU ex2
__device__ __forceinline__ float exp_s(float d) {
    float r;
    asm("ex2.approx.f32 %0, %1;" : "=f"(r) : "f"(43.2808512266689f * d));
    return r;
}

// ---------------------------------------------------------------------------
// Kernel 0: label dtype detect (touches only first 8KB; safe either way)
// ---------------------------------------------------------------------------
__global__ void detect_label_kernel(const int* __restrict__ lab) {
    __shared__ int any;
    if (threadIdx.x == 0) any = 0;
    __syncthreads();
    int v = 0;
    for (int i = threadIdx.x; i < 1024; i += blockDim.x) v |= lab[2 * i + 1];
    if (v) atomicOr(&any, 1);
    __syncthreads();
    if (threadIdx.x == 0) g_lab32 = (any != 0) ? 1 : 0;
}

// ---------------------------------------------------------------------------
// Kernel 0b: W (f32) -> g_wbf (bf16), permuted per k16 block so a B fragment
// (k pairs {2qt,2qt+1} and {2qt+8,2qt+9}) is one aligned 8-byte word pair.
// Word order per k16: (0,1)(8,9)(2,3)(10,11)(4,5)(12,13)(6,7)(14,15).
// ---------------------------------------------------------------------------
__global__ void convertW_kernel(const float* __restrict__ W) {
    int idx = blockIdx.x * blockDim.x + threadIdx.x;   // (cls, ks) pair
    if (idx >= CPAD * 12) return;
    int cls = idx / 12, ks = idx % 12;
    int cr = cls < C_CLS ? cls : C_CLS - 1;
    const float* wr = W + (size_t)cr * D_DIM + ks * 16;
    float v[16];
#pragma unroll
    for (int j = 0; j < 4; j++) {
        float4 t = ((const float4*)wr)[j];
        v[4 * j] = t.x; v[4 * j + 1] = t.y; v[4 * j + 2] = t.z; v[4 * j + 3] = t.w;
    }
    const int ps[8] = {0, 8, 2, 10, 4, 12, 6, 14};
    uint32_t o[8];
#pragma unroll
    for (int j = 0; j < 8; j++) o[j] = bfpack(v[ps[j]], v[ps[j] + 1]);
    uint4* dst = (uint4*)(g_wbf + (size_t)cls * D_DIM + ks * 16);
    dst[0] = make_uint4(o[0], o[1], o[2], o[3]);
    dst[1] = make_uint4(o[4], o[5], o[6], o[7]);
}

// ---------------------------------------------------------------------------
// Kernel 1: row normalize + exact target logit (fp32)
// ---------------------------------------------------------------------------
__global__ void norm_tgt_kernel(const float* __restrict__ x,
                                const float* __restrict__ W,
                                const void* __restrict__ label) {
    int warp = (blockIdx.x * blockDim.x + threadIdx.x) >> 5;
    int lane = threadIdx.x & 31;
    if (warp >= N_ROWS) return;

    const float* xr = x + (size_t)warp * D_DIM;
    float xv[6], ss = 0.f;
#pragma unroll
    for (int j = 0; j < 6; j++) { xv[j] = xr[lane + 32 * j]; ss += xv[j] * xv[j]; }
#pragma unroll
    for (int o = 16; o; o >>= 1) ss += __shfl_xor_sync(0xffffffffu, ss, o);
    float inv = rsqrtf(ss);

    long long li = g_lab32 ? (long long)((const int*)label)[warp]
                           : ((const long long*)label)[warp];
    if (li < 0) li = 0;
    if (li >= C_CLS) li = C_CLS - 1;

    const float* wr = W + (size_t)li * D_DIM;
    float dot = 0.f;
#pragma unroll
    for (int j = 0; j < 6; j++) {
        g_xn[(size_t)warp * D_DIM + lane + 32 * j] = xv[j] * inv;
        dot += xv[j] * wr[lane + 32 * j];
    }
#pragma unroll
    for (int o = 16; o; o >>= 1) dot += __shfl_xor_sync(0xffffffffu, dot, o);
    if (lane == 0) g_tgt[warp] = dot * inv;
}

// ---------------------------------------------------------------------------
// Kernel 2: bf16 mma.sync m16n8k16 GEMM, 128 rows x 256 classes/tile, K=192.
// 3-stage cp.async bf16 B pipeline; A pre-packed bf16 fragments (LDS.128);
// MUFU exp epilogue in registers per stripe.
//   warp grid 2(m) x 4(n); warp tile 64x64; 4(mt) x 8(nt) fragments, k16 steps.
// ---------------------------------------------------------------------------
__global__ void __launch_bounds__(256, 1) gemm_lse_mma(const float* __restrict__ W) {
    extern __shared__ uint32_t smw[];
    uint4*    As4 = (uint4*)smw;          // [96 frags][32 lanes]
    uint32_t* Bs  = smw + A_WORDS;        // 3 x [256][B_STRIDE_W]

    const int tid  = threadIdx.x;
    const int wid  = tid >> 5;
    const int lane = tid & 31;
    const int wm = wid >> 2, wn = wid & 3;
    const int qid = lane >> 2, qt = lane & 3;
    const int rowBase = blockIdx.y * 128;
    const int ct0 = blockIdx.x;

    // ---- stage A once as bf16 m16n8k16 fragments ----
    // frag f = fm*12 + ks; fm = 16-row group (0..7), ks = k16 step (0..11)
    for (int f = wid; f < 96; f += 8) {
        int fm = f / 12, ks = f % 12;
        const float* b0 = g_xn + (size_t)(rowBase + fm * 16 + qid) * D_DIM + ks * 16 + 2 * qt;
        const float* b8 = b0 + 8 * D_DIM;
        As4[f * 32 + lane] = make_uint4(
            bfpack(b0[0], b0[1]), bfpack(b8[0], b8[1]),
            bfpack(b0[8], b0[9]), bfpack(b8[8], b8[9]));
    }

    // B chunk loader: chunk c (32 k = 2 ksteps) of tile ct into stage buf
    auto loadB = [&](int ct, int c, int buf) {
        uint32_t* bs = Bs + buf * B_WORDS;
        int clsBase = ct * B_CLS;
#pragma unroll
        for (int it = 0; it < 4; it++) {
            int i = tid + it * 256;          // 1024 16B chunks
            int r = i >> 2, q = i & 3;
            int cls = clsBase + r;           // CPAD-padded, always valid in g_wbf
            cp16(smem_u32(bs + r * B_STRIDE_W + q * 4),
                 g_wbf + (size_t)cls * D_DIM + c * 32 + q * 8);
        }
        CP_COMMIT();
    };

    const int ntiles = (NT256 - 1 - ct0) / STRIPES + 1;
    const int total  = ntiles * 6;

    loadB(ct0, 0, 0);
    if (total > 1) loadB(ct0, 1, 1);

    float rsum[4][2] = {};
    float acc[4][8][4];

    for (int g = 0; g < total; ++g) {
        const int c  = g % 6;
        const int ct = ct0 + (g / 6) * STRIPES;

        if (g == total - 1) { CP_WAIT(0); } else { CP_WAIT(1); }
        __syncthreads();

        if (g + 2 < total) {
            int gn = g + 2;
            loadB(ct0 + (gn / 6) * STRIPES, gn % 6, gn % 3);
        }

        if (c == 0) {
#pragma unroll
            for (int mt = 0; mt < 4; mt++)
#pragma unroll
                for (int nt = 0; nt < 8; nt++)
#pragma unroll
                    for (int e = 0; e < 4; e++) acc[mt][nt][e] = 0.f;
        }

        const uint32_t* bs = Bs + (g % 3) * B_WORDS;
        const uint4* af = As4 + (wm * 4) * 12 * 32 + c * 2 * 32 + lane;
#pragma unroll
        for (int ksin = 0; ksin < 2; ksin++) {
            uint4 a[4];
#pragma unroll
            for (int mt = 0; mt < 4; mt++)
                a[mt] = af[(mt * 12 + ksin) * 32];
#pragma unroll
            for (int nt = 0; nt < 8; nt++) {
                const uint2 b = *(const uint2*)(bs + (wn * 64 + nt * 8 + qid) * B_STRIDE_W
                                                + ksin * 8 + 2 * qt);
#pragma unroll
                for (int mt = 0; mt < 4; mt++)
                    mma16(acc[mt][nt], (const uint32_t*)&a[mt], b.x, b.y);
            }
        }

        if (c == 5) {
            if (ct != NT256 - 1) {
#pragma unroll
                for (int mt = 0; mt < 4; mt++)
#pragma unroll
                    for (int nt = 0; nt < 8; nt++) {
                        rsum[mt][0] += exp_s(acc[mt][nt][0]) + exp_s(acc[mt][nt][1]);
                        rsum[mt][1] += exp_s(acc[mt][nt][2]) + exp_s(acc[mt][nt][3]);
                    }
            } else {
#pragma unroll
                for (int mt = 0; mt < 4; mt++)
#pragma unroll
                    for (int nt = 0; nt < 8; nt++) {
                        int cls0 = ct * B_CLS + wn * 64 + nt * 8 + 2 * qt;
                        if (cls0 < C_CLS)     { rsum[mt][0] += exp_s(acc[mt][nt][0]);
                                                rsum[mt][1] += exp_s(acc[mt][nt][2]); }
                        if (cls0 + 1 < C_CLS) { rsum[mt][0] += exp_s(acc[mt][nt][1]);
                                                rsum[mt][1] += exp_s(acc[mt][nt][3]); }
                    }
            }
        }
    }

    // ---- one partial per (stripe, wn) per row ----
    const int cidx = blockIdx.x * 4 + wn;
#pragma unroll
    for (int mt = 0; mt < 4; mt++) {
        float sLo = rsum[mt][0], sHi = rsum[mt][1];
        sLo += __shfl_xor_sync(0xffffffffu, sLo, 1);
        sLo += __shfl_xor_sync(0xffffffffu, sLo, 2);
        sHi += __shfl_xor_sync(0xffffffffu, sHi, 1);
        sHi += __shfl_xor_sync(0xffffffffu, sHi, 2);
        if (qt == 0) {
            int row = rowBase + wm * 64 + mt * 16 + qid;
            g_psum[(size_t)row * NPART + cidx]       = sLo;
            g_psum[(size_t)(row + 8) * NPART + cidx] = sHi;
        }
    }
}

// ---------------------------------------------------------------------------
// Kernel 3: warp per row: sum 148 partials + margin correction
// ---------------------------------------------------------------------------
__global__ void combine_kernel() {
    int row  = blockIdx.x * 8 + (threadIdx.x >> 5);
    int lane = threadIdx.x & 31;
    const float* p = g_psum + (size_t)row * NPART;
    float s = 0.f;
    for (int c = lane; c < NPART; c += 32) s += p[c];
#pragma unroll
    for (int o = 16; o; o >>= 1) s += __shfl_xor_sync(0xffffffffu, s, o);
    if (lane == 0) {
        float tgt   = g_tgt[row];
        float numer = S_SCALE * (tgt - MARGIN);
        float scorr = s - expf(S_SCALE * tgt) + expf(numer);
        g_L[row] = numer - logf(scorr);
    }
}

// ---------------------------------------------------------------------------
// Kernel 4: mean
// ---------------------------------------------------------------------------
__global__ void final_kernel(float* __restrict__ out) {
    __shared__ float sm[1024];
    int t = threadIdx.x;
    sm[t] = g_L[t] + g_L[t + 1024];
    __syncthreads();
    for (int st = 512; st > 0; st >>= 1) {
        if (t < st) sm[t] += sm[t + st];
        __syncthreads();
    }
    if (t == 0) out[0] = -sm[0] / (float)N_ROWS;
}

// ---------------------------------------------------------------------------
extern "C" void kernel_launch(void* const* d_in, const int* in_sizes, int n_in,
                              void* d_out, int out_size) {
    (void)in_sizes; (void)n_in; (void)out_size;
    const float* x     = (const float*)d_in[0];
    const float* W     = (const float*)d_in[1];
    const void*  label = d_in[2];
    float* out = (float*)d_out;

    cudaFuncSetAttribute(gemm_lse_mma, cudaFuncAttributeMaxDynamicSharedMemorySize, SMEM_TOTAL);

    detect_label_kernel<<<1, 256>>>((const int*)label);
    convertW_kernel<<<(CPAD * 12 + 255) / 256, 256>>>(W);
    norm_tgt_kernel<<<N_ROWS / 8, 256>>>(x, W, label);

    dim3 grid(STRIPES, N_ROWS / 128);
    gemm_lse_mma<<<grid, 256, SMEM_TOTAL>>>(W);

    combine_kernel<<<N_ROWS / 8, 256>>>();
    final_kernel<<<1, 1024>>>(out);
}

// round 8
// speedup vs baseline: 7.9106x; 1.2285x over previous
#include <cuda_runtime.h>
#include <math.h>
#include <stdint.h>

// Problem constants
#define N_ROWS 2048
#define D_DIM  192
#define C_CLS  100000
#define S_SCALE 30.0f
#define MARGIN  0.2f

#define NT256 391         // ceil(100000/256) class tiles of 256
#define CPAD  100096      // NT256*256, padded class count
#define STRIPES 37        // grid (37,16) = 592 CTAs = 4 clean waves
#define NPART (STRIPES * 4)   // 148 partials per row
#define B_CLS 256
#define B_STRIDE_W 56     // words per class row (48 data + 8 pad); 56%32=24 -> conflict-free
#define A_WORDS (96 * 32 * 4)                 // 12288 words = 48 KB
#define B_WORDS (B_CLS * B_STRIDE_W)          // 14336 words = 56 KB per stage
#define SMEM_TOTAL ((A_WORDS + 3 * B_WORDS) * 4)   // 221184 B

// ---------------- scratch globals ----------------
__device__ __align__(16) float g_xn[N_ROWS * D_DIM];
__device__ __align__(16) unsigned short g_wbf[(size_t)CPAD * D_DIM];  // bf16, k-pair permuted
__device__ float g_tgt[N_ROWS];
__device__ float g_psum[(size_t)N_ROWS * NPART];
__device__ float g_L[N_ROWS];
__device__ int   g_lab32;

// ---------------- helpers (sm_80-level PTX only) ----------------
__device__ __forceinline__ uint32_t smem_u32(const void* p) {
    uint32_t a;
    asm("{ .reg .u64 t; cvta.to.shared.u64 t, %1; cvt.u32.u64 %0, t; }" : "=r"(a) : "l"(p));
    return a;
}
__device__ __forceinline__ void cp16(uint32_t dst, const void* src) {
    asm volatile("cp.async.cg.shared.global [%0], [%1], 16;" :: "r"(dst), "l"(src) : "memory");
}
#define CP_COMMIT() asm volatile("cp.async.commit_group;" ::: "memory")
#define CP_WAIT(n)  asm volatile("cp.async.wait_group %0;" :: "n"(n) : "memory")

// pack(lo, hi): bf16x2 register {hi:lo}
__device__ __forceinline__ uint32_t bfpack(float lo, float hi) {
    uint32_t r;
    asm("cvt.rn.bf16x2.f32 %0, %1, %2;" : "=r"(r) : "f"(hi), "f"(lo));
    return r;
}

__device__ __forceinline__ void mma16(float* c, const uint32_t* a, uint32_t b0, uint32_t b1) {
    asm volatile(
        "mma.sync.aligned.m16n8k16.row.col.f32.bf16.bf16.f32 "
        "{%0,%1,%2,%3}, {%4,%5,%6,%7}, {%8,%9}, {%0,%1,%2,%3};"
        : "+f"(c[0]), "+f"(c[1]), "+f"(c[2]), "+f"(c[3])
        : "r"(a[0]), "r"(a[1]), "r"(a[2]), "r"(a[3]), "r"(b0), "r"(b1));
}

// exp(S*d) = 2^(S*log2(e)*d) via MUFU ex2
__device__ __forceinline__ float exp_s(float d) {
    float r;
    asm("ex2.approx.f32 %0, %1;" : "=f"(r) : "f"(43.2808512266689f * d));
    return r;
}

// ---------------------------------------------------------------------------
// Kernel 0: label dtype detect (touches only first 8KB; safe either way)
// ---------------------------------------------------------------------------
__global__ void detect_label_kernel(const int* __restrict__ lab) {
    __shared__ int any;
    if (threadIdx.x == 0) any = 0;
    __syncthreads();
    int v = 0;
    for (int i = threadIdx.x; i < 1024; i += blockDim.x) v |= lab[2 * i + 1];
    if (v) atomicOr(&any, 1);
    __syncthreads();
    if (threadIdx.x == 0) g_lab32 = (any != 0) ? 1 : 0;
}

// ---------------------------------------------------------------------------
// Kernel 0b: W (f32) -> g_wbf (bf16), permuted per k16 block so a B fragment
// (k pairs {2qt,2qt+1} and {2qt+8,2qt+9}) is one aligned 8-byte word pair.
// Word order per k16: (0,1)(8,9)(2,3)(10,11)(4,5)(12,13)(6,7)(14,15).
// ---------------------------------------------------------------------------
__global__ void convertW_kernel(const float* __restrict__ W) {
    int idx = blockIdx.x * blockDim.x + threadIdx.x;   // (cls, ks) pair
    if (idx >= CPAD * 12) return;
    int cls = idx / 12, ks = idx % 12;
    int cr = cls < C_CLS ? cls : C_CLS - 1;
    const float* wr = W + (size_t)cr * D_DIM + ks * 16;
    float v[16];
#pragma unroll
    for (int j = 0; j < 4; j++) {
        float4 t = ((const float4*)wr)[j];
        v[4 * j] = t.x; v[4 * j + 1] = t.y; v[4 * j + 2] = t.z; v[4 * j + 3] = t.w;
    }
    const int ps[8] = {0, 8, 2, 10, 4, 12, 6, 14};
    uint32_t o[8];
#pragma unroll
    for (int j = 0; j < 8; j++) o[j] = bfpack(v[ps[j]], v[ps[j] + 1]);
    uint4* dst = (uint4*)(g_wbf + (size_t)cls * D_DIM + ks * 16);
    dst[0] = make_uint4(o[0], o[1], o[2], o[3]);
    dst[1] = make_uint4(o[4], o[5], o[6], o[7]);
}

// ---------------------------------------------------------------------------
// Kernel 1: row normalize + exact target logit (fp32)
// ---------------------------------------------------------------------------
__global__ void norm_tgt_kernel(const float* __restrict__ x,
                                const float* __restrict__ W,
                                const void* __restrict__ label) {
    int warp = (blockIdx.x * blockDim.x + threadIdx.x) >> 5;
    int lane = threadIdx.x & 31;
    if (warp >= N_ROWS) return;

    const float* xr = x + (size_t)warp * D_DIM;
    float xv[6], ss = 0.f;
#pragma unroll
    for (int j = 0; j < 6; j++) { xv[j] = xr[lane + 32 * j]; ss += xv[j] * xv[j]; }
#pragma unroll
    for (int o = 16; o; o >>= 1) ss += __shfl_xor_sync(0xffffffffu, ss, o);
    float inv = rsqrtf(ss);

    long long li = g_lab32 ? (long long)((const int*)label)[warp]
                           : ((const long long*)label)[warp];
    if (li < 0) li = 0;
    if (li >= C_CLS) li = C_CLS - 1;

    const float* wr = W + (size_t)li * D_DIM;
    float dot = 0.f;
#pragma unroll
    for (int j = 0; j < 6; j++) {
        g_xn[(size_t)warp * D_DIM + lane + 32 * j] = xv[j] * inv;
        dot += xv[j] * wr[lane + 32 * j];
    }
#pragma unroll
    for (int o = 16; o; o >>= 1) dot += __shfl_xor_sync(0xffffffffu, dot, o);
    if (lane == 0) g_tgt[warp] = dot * inv;
}

// ---------------------------------------------------------------------------
// Kernel 2: bf16 mma.sync m16n8k16 GEMM, 128 rows x 256 classes/tile, K=192.
// 96-k chunks (6 k16-steps): 2 barriers per tile, 192 MMAs per warp between
// barriers. 3-stage cp.async B pipeline; A pre-packed bf16 fragments
// (LDS.128); MUFU exp epilogue in registers per stripe.
//   warp grid 2(m) x 4(n); warp tile 64x64; 4(mt) x 8(nt) fragments.
// ---------------------------------------------------------------------------
__global__ void __launch_bounds__(256, 1) gemm_lse_mma() {
    extern __shared__ uint32_t smw[];
    uint4*    As4 = (uint4*)smw;          // [96 frags][32 lanes]
    uint32_t* Bs  = smw + A_WORDS;        // 3 x [256][B_STRIDE_W]

    const int tid  = threadIdx.x;
    const int wid  = tid >> 5;
    const int lane = tid & 31;
    const int wm = wid >> 2, wn = wid & 3;
    const int qid = lane >> 2, qt = lane & 3;
    const int rowBase = blockIdx.y * 128;
    const int ct0 = blockIdx.x;

    // ---- stage A once as bf16 m16n8k16 fragments ----
    // frag f = fm*12 + ks; fm = 16-row group (0..7), ks = k16 step (0..11)
    for (int f = wid; f < 96; f += 8) {
        int fm = f / 12, ks = f % 12;
        const float* b0 = g_xn + (size_t)(rowBase + fm * 16 + qid) * D_DIM + ks * 16 + 2 * qt;
        const float* b8 = b0 + 8 * D_DIM;
        As4[f * 32 + lane] = make_uint4(
            bfpack(b0[0], b0[1]), bfpack(b8[0], b8[1]),
            bfpack(b0[8], b0[9]), bfpack(b8[8], b8[9]));
    }

    // B chunk loader: chunk c (96 k = 6 ksteps = 12 uint4/class) into stage buf
    const uint4* gw4 = (const uint4*)g_wbf;   // 24 uint4 per class row
    auto loadB = [&](int ct, int c, int buf) {
        uint4* bs4 = (uint4*)(Bs + buf * B_WORDS);   // class stride 14 uint4
        int clsBase = ct * B_CLS;
        int rb = tid >> 2, qb = tid & 3;
#pragma unroll
        for (int it = 0; it < 12; it++) {
            int r = rb + (it >> 2) * 64;             // it/3 pattern via 4 groups of 3
            int q = (it & 3);
            // remap: iterate sub-chunk layout (3 q-groups x 4 class-groups)
            // use: class group = it % 4? keep simple exact mapping below
            (void)q;
            int grp = it / 3;          // 0..3 class quarter
            int sub = it % 3;          // 0..2 q-quarter
            r = rb + grp * 64;
            int qq = sub * 4 + qb;     // 0..11
            cp16(smem_u32(bs4 + r * 14 + qq),
                 gw4 + (size_t)(clsBase + r) * 24 + c * 12 + qq);
        }
        CP_COMMIT();
    };

    const int ntiles = (NT256 - 1 - ct0) / STRIPES + 1;
    const int total  = ntiles * 2;

    loadB(ct0, 0, 0);
    if (total > 1) loadB(ct0, 1, 1);

    float rsum[4][2] = {};
    float acc[4][8][4];

    for (int g = 0; g < total; ++g) {
        const int c  = g & 1;
        const int ct = ct0 + (g >> 1) * STRIPES;

        if (g == total - 1) { CP_WAIT(0); } else { CP_WAIT(1); }
        __syncthreads();

        if (g + 2 < total) {
            int gn = g + 2;
            loadB(ct0 + (gn >> 1) * STRIPES, gn & 1, gn % 3);
        }

        if (c == 0) {
#pragma unroll
            for (int mt = 0; mt < 4; mt++)
#pragma unroll
                for (int nt = 0; nt < 8; nt++)
#pragma unroll
                    for (int e = 0; e < 4; e++) acc[mt][nt][e] = 0.f;
        }

        const uint32_t* bs = Bs + (g % 3) * B_WORDS;
        const uint4* af = As4 + (wm * 4) * 12 * 32 + c * 6 * 32 + lane;
        const uint32_t* bbase = bs + (wn * 64 + qid) * B_STRIDE_W + 2 * qt;
#pragma unroll
        for (int ks = 0; ks < 6; ks++) {
            uint4 a[4];
#pragma unroll
            for (int mt = 0; mt < 4; mt++)
                a[mt] = af[(mt * 12 + ks) * 32];
#pragma unroll
            for (int nt = 0; nt < 8; nt++) {
                const uint2 b = *(const uint2*)(bbase + nt * 8 * B_STRIDE_W + ks * 8);
#pragma unroll
                for (int mt = 0; mt < 4; mt++)
                    mma16(acc[mt][nt], (const uint32_t*)&a[mt], b.x, b.y);
            }
        }

        if (c == 1) {
            if (ct != NT256 - 1) {
#pragma unroll
                for (int mt = 0; mt < 4; mt++)
#pragma unroll
                    for (int nt = 0; nt < 8; nt++) {
                        rsum[mt][0] += exp_s(acc[mt][nt][0]) + exp_s(acc[mt][nt][1]);
                        rsum[mt][1] += exp_s(acc[mt][nt][2]) + exp_s(acc[mt][nt][3]);
                    }
            } else {
#pragma unroll
                for (int mt = 0; mt < 4; mt++)
#pragma unroll
                    for (int nt = 0; nt < 8; nt++) {
                        int cls0 = ct * B_CLS + wn * 64 + nt * 8 + 2 * qt;
                        if (cls0 < C_CLS)     { rsum[mt][0] += exp_s(acc[mt][nt][0]);
                                                rsum[mt][1] += exp_s(acc[mt][nt][2]); }
                        if (cls0 + 1 < C_CLS) { rsum[mt][0] += exp_s(acc[mt][nt][1]);
                                                rsum[mt][1] += exp_s(acc[mt][nt][3]); }
                    }
            }
        }
    }

    // ---- one partial per (stripe, wn) per row ----
    const int cidx = blockIdx.x * 4 + wn;
#pragma unroll
    for (int mt = 0; mt < 4; mt++) {
        float sLo = rsum[mt][0], sHi = rsum[mt][1];
        sLo += __shfl_xor_sync(0xffffffffu, sLo, 1);
        sLo += __shfl_xor_sync(0xffffffffu, sLo, 2);
        sHi += __shfl_xor_sync(0xffffffffu, sHi, 1);
        sHi += __shfl_xor_sync(0xffffffffu, sHi, 2);
        if (qt == 0) {
            int row = rowBase + wm * 64 + mt * 16 + qid;
            g_psum[(size_t)row * NPART + cidx]       = sLo;
            g_psum[(size_t)(row + 8) * NPART + cidx] = sHi;
        }
    }
}

// ---------------------------------------------------------------------------
// Kernel 3: warp per row: sum 148 partials + margin correction
// ---------------------------------------------------------------------------
__global__ void combine_kernel() {
    int row  = blockIdx.x * 8 + (threadIdx.x >> 5);
    int lane = threadIdx.x & 31;
    const float* p = g_psum + (size_t)row * NPART;
    float s = 0.f;
    for (int c = lane; c < NPART; c += 32) s += p[c];
#pragma unroll
    for (int o = 16; o; o >>= 1) s += __shfl_xor_sync(0xffffffffu, s, o);
    if (lane == 0) {
        float tgt   = g_tgt[row];
        float numer = S_SCALE * (tgt - MARGIN);
        float scorr = s - expf(S_SCALE * tgt) + expf(numer);
        g_L[row] = numer - logf(scorr);
    }
}

// ---------------------------------------------------------------------------
// Kernel 4: mean
// ---------------------------------------------------------------------------
__global__ void final_kernel(float* __restrict__ out) {
    __shared__ float sm[1024];
    int t = threadIdx.x;
    sm[t] = g_L[t] + g_L[t + 1024];
    __syncthreads();
    for (int st = 512; st > 0; st >>= 1) {
        if (t < st) sm[t] += sm[t + st];
        __syncthreads();
    }
    if (t == 0) out[0] = -sm[0] / (float)N_ROWS;
}

// ---------------------------------------------------------------------------
extern "C" void kernel_launch(void* const* d_in, const int* in_sizes, int n_in,
                              void* d_out, int out_size) {
    (void)in_sizes; (void)n_in; (void)out_size;
    const float* x     = (const float*)d_in[0];
    const float* W     = (const float*)d_in[1];
    const void*  label = d_in[2];
    float* out = (float*)d_out;

    cudaFuncSetAttribute(gemm_lse_mma, cudaFuncAttributeMaxDynamicSharedMemorySize, SMEM_TOTAL);

    detect_label_kernel<<<1, 256>>>((const int*)label);
    convertW_kernel<<<(CPAD * 12 + 255) / 256, 256>>>(W);
    norm_tgt_kernel<<<N_ROWS / 8, 256>>>(x, W, label);

    dim3 grid(STRIPES, N_ROWS / 128);
    gemm_lse_mma<<<grid, 256, SMEM_TOTAL>>>();

    combine_kernel<<<N_ROWS / 8, 256>>>();
    final_kernel<<<1, 1024>>>(out);
}

// round 9
// speedup vs baseline: 8.2657x; 1.0449x over previous
#include <cuda_runtime.h>
#include <math.h>
#include <stdint.h>

// Problem constants
#define N_ROWS 2048
#define D_DIM  192
#define C_CLS  100000
#define S_SCALE 30.0f
#define MARGIN  0.2f

#define NT256 391         // ceil(100000/256) class tiles of 256
#define CPAD  100096      // NT256*256, padded class count
#define STRIPES 37        // grid (37,16) = 592 CTAs = 4 clean waves
#define NPART (STRIPES * 8)   // 296 partials per row (8 n-warps)
#define B_CLS 256
#define B_STRIDE_W 56     // words per class row (48 data + 8 pad)
#define A_WORDS (96 * 32 * 4)                 // 12288 words = 48 KB
#define B_WORDS (B_CLS * B_STRIDE_W)          // 14336 words = 56 KB per stage
#define SMEM_TOTAL ((A_WORDS + 3 * B_WORDS) * 4)   // 221184 B

// ---------------- scratch globals ----------------
__device__ __align__(16) float g_xn[N_ROWS * D_DIM];
__device__ __align__(16) unsigned short g_wbf[(size_t)CPAD * D_DIM];  // bf16, k-pair permuted
__device__ float g_tgt[N_ROWS];
__device__ float g_psum[(size_t)N_ROWS * NPART];
__device__ float g_L[N_ROWS];
__device__ int   g_lab32;

// ---------------- helpers (sm_80-level PTX only) ----------------
__device__ __forceinline__ uint32_t smem_u32(const void* p) {
    uint32_t a;
    asm("{ .reg .u64 t; cvta.to.shared.u64 t, %1; cvt.u32.u64 %0, t; }" : "=r"(a) : "l"(p));
    return a;
}
__device__ __forceinline__ void cp16(uint32_t dst, const void* src) {
    asm volatile("cp.async.cg.shared.global [%0], [%1], 16;" :: "r"(dst), "l"(src) : "memory");
}
#define CP_COMMIT() asm volatile("cp.async.commit_group;" ::: "memory")
#define CP_WAIT(n)  asm volatile("cp.async.wait_group %0;" :: "n"(n) : "memory")

// pack(lo, hi): bf16x2 register {hi:lo}
__device__ __forceinline__ uint32_t bfpack(float lo, float hi) {
    uint32_t r;
    asm("cvt.rn.bf16x2.f32 %0, %1, %2;" : "=r"(r) : "f"(hi), "f"(lo));
    return r;
}

__device__ __forceinline__ void mma16(float* c, const uint32_t* a, uint32_t b0, uint32_t b1) {
    asm volatile(
        "mma.sync.aligned.m16n8k16.row.col.f32.bf16.bf16.f32 "
        "{%0,%1,%2,%3}, {%4,%5,%6,%7}, {%8,%9}, {%0,%1,%2,%3};"
        : "+f"(c[0]), "+f"(c[1]), "+f"(c[2]), "+f"(c[3])
        : "r"(a[0]), "r"(a[1]), "r"(a[2]), "r"(a[3]), "r"(b0), "r"(b1));
}

// exp(S*d) = 2^(S*log2(e)*d) via MUFU ex2
__device__ __forceinline__ float exp_s(float d) {
    float r;
    asm("ex2.approx.f32 %0, %1;" : "=f"(r) : "f"(43.2808512266689f * d));
    return r;
}

// ---------------------------------------------------------------------------
// Kernel 0: label dtype detect (touches only first 8KB; safe either way)
// ---------------------------------------------------------------------------
__global__ void detect_label_kernel(const int* __restrict__ lab) {
    __shared__ int any;
    if (threadIdx.x == 0) any = 0;
    __syncthreads();
    int v = 0;
    for (int i = threadIdx.x; i < 1024; i += blockDim.x) v |= lab[2 * i + 1];
    if (v) atomicOr(&any, 1);
    __syncthreads();
    if (threadIdx.x == 0) g_lab32 = (any != 0) ? 1 : 0;
}

// ---------------------------------------------------------------------------
// Kernel 0b: W (f32) -> g_wbf (bf16), permuted per k16 block so a B fragment
// (k pairs {2qt,2qt+1} and {2qt+8,2qt+9}) is one aligned 8-byte word pair.
// Word order per k16: (0,1)(8,9)(2,3)(10,11)(4,5)(12,13)(6,7)(14,15).
// ---------------------------------------------------------------------------
__global__ void convertW_kernel(const float* __restrict__ W) {
    int idx = blockIdx.x * blockDim.x + threadIdx.x;   // (cls, ks) pair
    if (idx >= CPAD * 12) return;
    int cls = idx / 12, ks = idx % 12;
    int cr = cls < C_CLS ? cls : C_CLS - 1;
    const float* wr = W + (size_t)cr * D_DIM + ks * 16;
    float v[16];
#pragma unroll
    for (int j = 0; j < 4; j++) {
        float4 t = ((const float4*)wr)[j];
        v[4 * j] = t.x; v[4 * j + 1] = t.y; v[4 * j + 2] = t.z; v[4 * j + 3] = t.w;
    }
    const int ps[8] = {0, 8, 2, 10, 4, 12, 6, 14};
    uint32_t o[8];
#pragma unroll
    for (int j = 0; j < 8; j++) o[j] = bfpack(v[ps[j]], v[ps[j] + 1]);
    uint4* dst = (uint4*)(g_wbf + (size_t)cls * D_DIM + ks * 16);
    dst[0] = make_uint4(o[0], o[1], o[2], o[3]);
    dst[1] = make_uint4(o[4], o[5], o[6], o[7]);
}

// ---------------------------------------------------------------------------
// Kernel 1: row normalize + exact target logit (fp32)
// ---------------------------------------------------------------------------
__global__ void norm_tgt_kernel(const float* __restrict__ x,
                                const float* __restrict__ W,
                                const void* __restrict__ label) {
    int warp = (blockIdx.x * blockDim.x + threadIdx.x) >> 5;
    int lane = threadIdx.x & 31;
    if (warp >= N_ROWS) return;

    const float* xr = x + (size_t)warp * D_DIM;
    float xv[6], ss = 0.f;
#pragma unroll
    for (int j = 0; j < 6; j++) { xv[j] = xr[lane + 32 * j]; ss += xv[j] * xv[j]; }
#pragma unroll
    for (int o = 16; o; o >>= 1) ss += __shfl_xor_sync(0xffffffffu, ss, o);
    float inv = rsqrtf(ss);

    long long li = g_lab32 ? (long long)((const int*)label)[warp]
                           : ((const long long*)label)[warp];
    if (li < 0) li = 0;
    if (li >= C_CLS) li = C_CLS - 1;

    const float* wr = W + (size_t)li * D_DIM;
    float dot = 0.f;
#pragma unroll
    for (int j = 0; j < 6; j++) {
        g_xn[(size_t)warp * D_DIM + lane + 32 * j] = xv[j] * inv;
        dot += xv[j] * wr[lane + 32 * j];
    }
#pragma unroll
    for (int o = 16; o; o >>= 1) dot += __shfl_xor_sync(0xffffffffu, dot, o);
    if (lane == 0) g_tgt[warp] = dot * inv;
}

// ---------------------------------------------------------------------------
// Kernel 2: bf16 mma.sync m16n8k16 GEMM, 128 rows x 256 classes/tile, K=192.
// 512 threads, 16 warps (4/SMSP) for latency hiding.
//   warp grid 2(m) x 8(n); warp tile 64x32; 4(mt) x 4(nt) fragments.
// 96-k chunks, 3-stage cp.async pipeline, MUFU exp epilogue in registers.
// ---------------------------------------------------------------------------
__global__ void __launch_bounds__(512, 1) gemm_lse_mma() {
    extern __shared__ uint32_t smw[];
    uint4*    As4 = (uint4*)smw;          // [96 frags][32 lanes]
    uint32_t* Bs  = smw + A_WORDS;        // 3 x [256][B_STRIDE_W]

    const int tid  = threadIdx.x;
    const int wid  = tid >> 5;
    const int lane = tid & 31;
    const int wm = wid >> 3, wn = wid & 7;
    const int qid = lane >> 2, qt = lane & 3;
    const int rowBase = blockIdx.y * 128;
    const int ct0 = blockIdx.x;

    // ---- stage A once as bf16 m16n8k16 fragments ----
    // frag f = fm*12 + ks; fm = 16-row group (0..7), ks = k16 step (0..11)
    for (int f = wid; f < 96; f += 16) {
        int fm = f / 12, ks = f % 12;
        const float* b0 = g_xn + (size_t)(rowBase + fm * 16 + qid) * D_DIM + ks * 16 + 2 * qt;
        const float* b8 = b0 + 8 * D_DIM;
        As4[f * 32 + lane] = make_uint4(
            bfpack(b0[0], b0[1]), bfpack(b8[0], b8[1]),
            bfpack(b0[8], b0[9]), bfpack(b8[8], b8[9]));
    }

    // B chunk loader: chunk c (96 k = 6 ksteps = 12 uint4/class) into stage buf
    const uint4* gw4 = (const uint4*)g_wbf;   // 24 uint4 per class row
    auto loadB = [&](int ct, int c, int buf) {
        uint4* bs4 = (uint4*)(Bs + buf * B_WORDS);   // class stride 14 uint4
        int clsBase = ct * B_CLS;
        int rb = tid >> 2, qb = tid & 3;             // rb 0..127
#pragma unroll
        for (int it = 0; it < 6; it++) {
            int grp = it / 3;          // 0..1 class half
            int sub = it % 3;          // 0..2 q-third
            int r = rb + grp * 128;
            int qq = sub * 4 + qb;     // 0..11
            cp16(smem_u32(bs4 + r * 14 + qq),
                 gw4 + (size_t)(clsBase + r) * 24 + c * 12 + qq);
        }
        CP_COMMIT();
    };

    const int ntiles = (NT256 - 1 - ct0) / STRIPES + 1;
    const int total  = ntiles * 2;

    loadB(ct0, 0, 0);
    if (total > 1) loadB(ct0, 1, 1);

    float rsum[4][2] = {};
    float acc[4][4][4];

    for (int g = 0; g < total; ++g) {
        const int c  = g & 1;
        const int ct = ct0 + (g >> 1) * STRIPES;

        if (g == total - 1) { CP_WAIT(0); } else { CP_WAIT(1); }
        __syncthreads();

        if (g + 2 < total) {
            int gn = g + 2;
            loadB(ct0 + (gn >> 1) * STRIPES, gn & 1, gn % 3);
        }

        if (c == 0) {
#pragma unroll
            for (int mt = 0; mt < 4; mt++)
#pragma unroll
                for (int nt = 0; nt < 4; nt++)
#pragma unroll
                    for (int e = 0; e < 4; e++) acc[mt][nt][e] = 0.f;
        }

        const uint32_t* bs = Bs + (g % 3) * B_WORDS;
        const uint4* af = As4 + (wm * 4) * 12 * 32 + c * 6 * 32 + lane;
        const uint32_t* bbase = bs + (wn * 32 + qid) * B_STRIDE_W + 2 * qt;
#pragma unroll
        for (int ks = 0; ks < 6; ks++) {
            uint4 a[4];
#pragma unroll
            for (int mt = 0; mt < 4; mt++)
                a[mt] = af[(mt * 12 + ks) * 32];
#pragma unroll
            for (int nt = 0; nt < 4; nt++) {
                const uint2 b = *(const uint2*)(bbase + nt * 8 * B_STRIDE_W + ks * 8);
#pragma unroll
                for (int mt = 0; mt < 4; mt++)
                    mma16(acc[mt][nt], (const uint32_t*)&a[mt], b.x, b.y);
            }
        }

        if (c == 1) {
            if (ct != NT256 - 1) {
#pragma unroll
                for (int mt = 0; mt < 4; mt++)
#pragma unroll
                    for (int nt = 0; nt < 4; nt++) {
                        rsum[mt][0] += exp_s(acc[mt][nt][0]) + exp_s(acc[mt][nt][1]);
                        rsum[mt][1] += exp_s(acc[mt][nt][2]) + exp_s(acc[mt][nt][3]);
                    }
            } else {
#pragma unroll
                for (int mt = 0; mt < 4; mt++)
#pragma unroll
                    for (int nt = 0; nt < 4; nt++) {
                        int cls0 = ct * B_CLS + wn * 32 + nt * 8 + 2 * qt;
                        if (cls0 < C_CLS)     { rsum[mt][0] += exp_s(acc[mt][nt][0]);
                                                rsum[mt][1] += exp_s(acc[mt][nt][2]); }
                        if (cls0 + 1 < C_CLS) { rsum[mt][0] += exp_s(acc[mt][nt][1]);
                                                rsum[mt][1] += exp_s(acc[mt][nt][3]); }
                    }
            }
        }
    }

    // ---- one partial per (stripe, wn) per row ----
    const int cidx = blockIdx.x * 8 + wn;
#pragma unroll
    for (int mt = 0; mt < 4; mt++) {
        float sLo = rsum[mt][0], sHi = rsum[mt][1];
        sLo += __shfl_xor_sync(0xffffffffu, sLo, 1);
        sLo += __shfl_xor_sync(0xffffffffu, sLo, 2);
        sHi += __shfl_xor_sync(0xffffffffu, sHi, 1);
        sHi += __shfl_xor_sync(0xffffffffu, sHi, 2);
        if (qt == 0) {
            int row = rowBase + wm * 64 + mt * 16 + qid;
            g_psum[(size_t)row * NPART + cidx]       = sLo;
            g_psum[(size_t)(row + 8) * NPART + cidx] = sHi;
        }
    }
}

// ---------------------------------------------------------------------------
// Kernel 3: warp per row: sum 296 partials + margin correction
// ---------------------------------------------------------------------------
__global__ void combine_kernel() {
    int row  = blockIdx.x * 8 + (threadIdx.x >> 5);
    int lane = threadIdx.x & 31;
    const float* p = g_psum + (size_t)row * NPART;
    float s = 0.f;
    for (int c = lane; c < NPART; c += 32) s += p[c];
#pragma unroll
    for (int o = 16; o; o >>= 1) s += __shfl_xor_sync(0xffffffffu, s, o);
    if (lane == 0) {
        float tgt   = g_tgt[row];
        float numer = S_SCALE * (tgt - MARGIN);
        float scorr = s - expf(S_SCALE * tgt) + expf(numer);
        g_L[row] = numer - logf(scorr);
    }
}

// ---------------------------------------------------------------------------
// Kernel 4: mean
// ---------------------------------------------------------------------------
__global__ void final_kernel(float* __restrict__ out) {
    __shared__ float sm[1024];
    int t = threadIdx.x;
    sm[t] = g_L[t] + g_L[t + 1024];
    __syncthreads();
    for (int st = 512; st > 0; st >>= 1) {
        if (t < st) sm[t] += sm[t + st];
        __syncthreads();
    }
    if (t == 0) out[0] = -sm[0] / (float)N_ROWS;
}

// ---------------------------------------------------------------------------
extern "C" void kernel_launch(void* const* d_in, const int* in_sizes, int n_in,
                              void* d_out, int out_size) {
    (void)in_sizes; (void)n_in; (void)out_size;
    const float* x     = (const float*)d_in[0];
    const float* W     = (const float*)d_in[1];
    const void*  label = d_in[2];
    float* out = (float*)d_out;

    cudaFuncSetAttribute(gemm_lse_mma, cudaFuncAttributeMaxDynamicSharedMemorySize, SMEM_TOTAL);

    detect_label_kernel<<<1, 256>>>((const int*)label);
    convertW_kernel<<<(CPAD * 12 + 255) / 256, 256>>>(W);
    norm_tgt_kernel<<<N_ROWS / 8, 256>>>(x, W, label);

    dim3 grid(STRIPES, N_ROWS / 128);
    gemm_lse_mma<<<grid, 512, SMEM_TOTAL>>>();

    combine_kernel<<<N_ROWS / 8, 256>>>();
    final_kernel<<<1, 1024>>>(out);
}

// round 10
// speedup vs baseline: 8.9085x; 1.0778x over previous
#include <cuda_runtime.h>
#include <math.h>
#include <stdint.h>

// Problem constants
#define N_ROWS 2048
#define D_DIM  192
#define C_CLS  100000
#define S_SCALE 30.0f
#define MARGIN  0.2f

#define NT128 782         // class tiles of 128 (782*128 = 100096)
#define CPAD  100096
#define STRIPES 74        // grid (74,16) = 1184 CTAs = 4 waves @ 2 CTA/SM
#define NPART (STRIPES * 4)   // 296 partials per row
#define B_CLS 128
#define B_STRIDE_W 56     // words per class row (48 data + 8 pad)
#define A_WORDS (96 * 32 * 4)                 // 12288 words = 48 KB
#define B_WORDS (B_CLS * B_STRIDE_W)          // 7168 words = 28 KB per stage
#define SMEM_TOTAL ((A_WORDS + 2 * B_WORDS) * 4)   // 106496 B

// ---------------- scratch globals ----------------
__device__ __align__(16) float g_xn[N_ROWS * D_DIM];
__device__ __align__(16) unsigned short g_wbf[(size_t)CPAD * D_DIM];  // bf16, k-pair permuted
__device__ float g_tgt[N_ROWS];
__device__ float g_psum[(size_t)N_ROWS * NPART];
__device__ float g_L[N_ROWS];
__device__ int   g_lab32;

// ---------------- helpers (sm_80-level PTX only) ----------------
__device__ __forceinline__ uint32_t smem_u32(const void* p) {
    uint32_t a;
    asm("{ .reg .u64 t; cvta.to.shared.u64 t, %1; cvt.u32.u64 %0, t; }" : "=r"(a) : "l"(p));
    return a;
}
__device__ __forceinline__ void cp16(uint32_t dst, const void* src) {
    asm volatile("cp.async.cg.shared.global [%0], [%1], 16;" :: "r"(dst), "l"(src) : "memory");
}
#define CP_COMMIT() asm volatile("cp.async.commit_group;" ::: "memory")
#define CP_WAIT(n)  asm volatile("cp.async.wait_group %0;" :: "n"(n) : "memory")

// pack(lo, hi): bf16x2 register {hi:lo}
__device__ __forceinline__ uint32_t bfpack(float lo, float hi) {
    uint32_t r;
    asm("cvt.rn.bf16x2.f32 %0, %1, %2;" : "=r"(r) : "f"(hi), "f"(lo));
    return r;
}

__device__ __forceinline__ void mma16(float* c, const uint32_t* a, uint32_t b0, uint32_t b1) {
    asm volatile(
        "mma.sync.aligned.m16n8k16.row.col.f32.bf16.bf16.f32 "
        "{%0,%1,%2,%3}, {%4,%5,%6,%7}, {%8,%9}, {%0,%1,%2,%3};"
        : "+f"(c[0]), "+f"(c[1]), "+f"(c[2]), "+f"(c[3])
        : "r"(a[0]), "r"(a[1]), "r"(a[2]), "r"(a[3]), "r"(b0), "r"(b1));
}

// exp(S*d) = 2^(S*log2(e)*d) via MUFU ex2
__device__ __forceinline__ float exp_s(float d) {
    float r;
    asm("ex2.approx.f32 %0, %1;" : "=f"(r) : "f"(43.2808512266689f * d));
    return r;
}

// ---------------------------------------------------------------------------
// Kernel 0: label dtype detect (touches only first 8KB; safe either way)
// ---------------------------------------------------------------------------
__global__ void detect_label_kernel(const int* __restrict__ lab) {
    __shared__ int any;
    if (threadIdx.x == 0) any = 0;
    __syncthreads();
    int v = 0;
    for (int i = threadIdx.x; i < 1024; i += blockDim.x) v |= lab[2 * i + 1];
    if (v) atomicOr(&any, 1);
    __syncthreads();
    if (threadIdx.x == 0) g_lab32 = (any != 0) ? 1 : 0;
}

// ---------------------------------------------------------------------------
// Kernel 0b: W (f32) -> g_wbf (bf16), permuted per k16 block so a B fragment
// (k pairs {2qt,2qt+1} and {2qt+8,2qt+9}) is one aligned 8-byte word pair.
// Word order per k16: (0,1)(8,9)(2,3)(10,11)(4,5)(12,13)(6,7)(14,15).
// ---------------------------------------------------------------------------
__global__ void convertW_kernel(const float* __restrict__ W) {
    int idx = blockIdx.x * blockDim.x + threadIdx.x;   // (cls, ks) pair
    if (idx >= CPAD * 12) return;
    int cls = idx / 12, ks = idx % 12;
    int cr = cls < C_CLS ? cls : C_CLS - 1;
    const float* wr = W + (size_t)cr * D_DIM + ks * 16;
    float v[16];
#pragma unroll
    for (int j = 0; j < 4; j++) {
        float4 t = ((const float4*)wr)[j];
        v[4 * j] = t.x; v[4 * j + 1] = t.y; v[4 * j + 2] = t.z; v[4 * j + 3] = t.w;
    }
    const int ps[8] = {0, 8, 2, 10, 4, 12, 6, 14};
    uint32_t o[8];
#pragma unroll
    for (int j = 0; j < 8; j++) o[j] = bfpack(v[ps[j]], v[ps[j] + 1]);
    uint4* dst = (uint4*)(g_wbf + (size_t)cls * D_DIM + ks * 16);
    dst[0] = make_uint4(o[0], o[1], o[2], o[3]);
    dst[1] = make_uint4(o[4], o[5], o[6], o[7]);
}

// ---------------------------------------------------------------------------
// Kernel 1: row normalize + exact target logit (fp32)
// ---------------------------------------------------------------------------
__global__ void norm_tgt_kernel(const float* __restrict__ x,
                                const float* __restrict__ W,
                                const void* __restrict__ label) {
    int warp = (blockIdx.x * blockDim.x + threadIdx.x) >> 5;
    int lane = threadIdx.x & 31;
    if (warp >= N_ROWS) return;

    const float* xr = x + (size_t)warp * D_DIM;
    float xv[6], ss = 0.f;
#pragma unroll
    for (int j = 0; j < 6; j++) { xv[j] = xr[lane + 32 * j]; ss += xv[j] * xv[j]; }
#pragma unroll
    for (int o = 16; o; o >>= 1) ss += __shfl_xor_sync(0xffffffffu, ss, o);
    float inv = rsqrtf(ss);

    long long li = g_lab32 ? (long long)((const int*)label)[warp]
                           : ((const long long*)label)[warp];
    if (li < 0) li = 0;
    if (li >= C_CLS) li = C_CLS - 1;

    const float* wr = W + (size_t)li * D_DIM;
    float dot = 0.f;
#pragma unroll
    for (int j = 0; j < 6; j++) {
        g_xn[(size_t)warp * D_DIM + lane + 32 * j] = xv[j] * inv;
        dot += xv[j] * wr[lane + 32 * j];
    }
#pragma unroll
    for (int o = 16; o; o >>= 1) dot += __shfl_xor_sync(0xffffffffu, dot, o);
    if (lane == 0) g_tgt[warp] = dot * inv;
}

// ---------------------------------------------------------------------------
// Kernel 2: bf16 mma.sync m16n8k16 GEMM, 128 rows x 128 classes per CTA tile.
// 256 threads, 8 warps, 2 CTAs/SM (independent barrier domains decorrelate
// LDS bursts so the tensor pipe stays fed). 96-k chunks, 2-stage cp.async.
//   warp grid 2(m) x 4(n); warp tile 64x32; 4(mt) x 4(nt) fragments.
// ---------------------------------------------------------------------------
__global__ void __launch_bounds__(256, 2) gemm_lse_mma() {
    extern __shared__ uint32_t smw[];
    uint4*    As4 = (uint4*)smw;          // [96 frags][32 lanes]
    uint32_t* Bs  = smw + A_WORDS;        // 2 x [128][B_STRIDE_W]

    const int tid  = threadIdx.x;
    const int wid  = tid >> 5;
    const int lane = tid & 31;
    const int wm = wid >> 2, wn = wid & 3;
    const int qid = lane >> 2, qt = lane & 3;
    const int rowBase = blockIdx.y * 128;
    const int ct0 = blockIdx.x;

    // ---- stage A once as bf16 m16n8k16 fragments ----
    // frag f = fm*12 + ks; fm = 16-row group (0..7), ks = k16 step (0..11)
    for (int f = wid; f < 96; f += 8) {
        int fm = f / 12, ks = f % 12;
        const float* b0 = g_xn + (size_t)(rowBase + fm * 16 + qid) * D_DIM + ks * 16 + 2 * qt;
        const float* b8 = b0 + 8 * D_DIM;
        As4[f * 32 + lane] = make_uint4(
            bfpack(b0[0], b0[1]), bfpack(b8[0], b8[1]),
            bfpack(b0[8], b0[9]), bfpack(b8[8], b8[9]));
    }

    // B chunk loader: chunk c (96 k = 6 ksteps = 12 uint4/class) into stage buf
    const uint4* gw4 = (const uint4*)g_wbf;   // 24 uint4 per class row
    auto loadB = [&](int ct, int c, int buf) {
        uint4* bs4 = (uint4*)(Bs + buf * B_WORDS);   // class stride 14 uint4
        int clsBase = ct * B_CLS;
        int rb = tid >> 2, qb = tid & 3;             // rb 0..63
#pragma unroll
        for (int it = 0; it < 6; it++) {
            int grp = it / 3;          // class half (0..1)
            int sub = it % 3;          // q third (0..2)
            int r = rb + grp * 64;
            int qq = sub * 4 + qb;     // 0..11
            cp16(smem_u32(bs4 + r * 14 + qq),
                 gw4 + (size_t)(clsBase + r) * 24 + c * 12 + qq);
        }
        CP_COMMIT();
    };

    const int ntiles = (NT128 - 1 - ct0) / STRIPES + 1;
    const int total  = ntiles * 2;

    loadB(ct0, 0, 0);    // chunk 0 in flight

    float rsum[4][2] = {};
    float acc[4][4][4];

    for (int g = 0; g < total; ++g) {
        const int c  = g & 1;
        const int ct = ct0 + (g >> 1) * STRIPES;

        CP_WAIT(0);        // chunk g resident (issued one full chunk ago)
        __syncthreads();   // visible to all; prior readers of other buffer done

        if (g + 1 < total) {
            int gn = g + 1;
            loadB(ct0 + (gn >> 1) * STRIPES, gn & 1, gn & 1);
        }

        if (c == 0) {
#pragma unroll
            for (int mt = 0; mt < 4; mt++)
#pragma unroll
                for (int nt = 0; nt < 4; nt++)
#pragma unroll
                    for (int e = 0; e < 4; e++) acc[mt][nt][e] = 0.f;
        }

        const uint32_t* bs = Bs + (g & 1) * B_WORDS;
        const uint4* af = As4 + (wm * 4) * 12 * 32 + c * 6 * 32 + lane;
        const uint32_t* bbase = bs + (wn * 32 + qid) * B_STRIDE_W + 2 * qt;
#pragma unroll
        for (int ks = 0; ks < 6; ks++) {
            uint4 a[4];
#pragma unroll
            for (int mt = 0; mt < 4; mt++)
                a[mt] = af[(mt * 12 + ks) * 32];
#pragma unroll
            for (int nt = 0; nt < 4; nt++) {
                const uint2 b = *(const uint2*)(bbase + nt * 8 * B_STRIDE_W + ks * 8);
#pragma unroll
                for (int mt = 0; mt < 4; mt++)
                    mma16(acc[mt][nt], (const uint32_t*)&a[mt], b.x, b.y);
            }
        }

        if (c == 1) {
            if (ct != NT128 - 1) {
#pragma unroll
                for (int mt = 0; mt < 4; mt++)
#pragma unroll
                    for (int nt = 0; nt < 4; nt++) {
                        rsum[mt][0] += exp_s(acc[mt][nt][0]) + exp_s(acc[mt][nt][1]);
                        rsum[mt][1] += exp_s(acc[mt][nt][2]) + exp_s(acc[mt][nt][3]);
                    }
            } else {
#pragma unroll
                for (int mt = 0; mt < 4; mt++)
#pragma unroll
                    for (int nt = 0; nt < 4; nt++) {
                        int cls0 = ct * B_CLS + wn * 32 + nt * 8 + 2 * qt;
                        if (cls0 < C_CLS)     { rsum[mt][0] += exp_s(acc[mt][nt][0]);
                                                rsum[mt][1] += exp_s(acc[mt][nt][2]); }
                        if (cls0 + 1 < C_CLS) { rsum[mt][0] += exp_s(acc[mt][nt][1]);
                                                rsum[mt][1] += exp_s(acc[mt][nt][3]); }
                    }
            }
        }
    }

    // ---- one partial per (stripe, wn) per row ----
    const int cidx = blockIdx.x * 4 + wn;
#pragma unroll
    for (int mt = 0; mt < 4; mt++) {
        float sLo = rsum[mt][0], sHi = rsum[mt][1];
        sLo += __shfl_xor_sync(0xffffffffu, sLo, 1);
        sLo += __shfl_xor_sync(0xffffffffu, sLo, 2);
        sHi += __shfl_xor_sync(0xffffffffu, sHi, 1);
        sHi += __shfl_xor_sync(0xffffffffu, sHi, 2);
        if (qt == 0) {
            int row = rowBase + wm * 64 + mt * 16 + qid;
            g_psum[(size_t)row * NPART + cidx]       = sLo;
            g_psum[(size_t)(row + 8) * NPART + cidx] = sHi;
        }
    }
}

// ---------------------------------------------------------------------------
// Kernel 3: warp per row: sum 296 partials + margin correction
// ---------------------------------------------------------------------------
__global__ void combine_kernel() {
    int row  = blockIdx.x * 8 + (threadIdx.x >> 5);
    int lane = threadIdx.x & 31;
    const float* p = g_psum + (size_t)row * NPART;
    float s = 0.f;
    for (int c = lane; c < NPART; c += 32) s += p[c];
#pragma unroll
    for (int o = 16; o; o >>= 1) s += __shfl_xor_sync(0xffffffffu, s, o);
    if (lane == 0) {
        float tgt   = g_tgt[row];
        float numer = S_SCALE * (tgt - MARGIN);
        float scorr = s - expf(S_SCALE * tgt) + expf(numer);
        g_L[row] = numer - logf(scorr);
    }
}

// ---------------------------------------------------------------------------
// Kernel 4: mean
// ---------------------------------------------------------------------------
__global__ void final_kernel(float* __restrict__ out) {
    __shared__ float sm[1024];
    int t = threadIdx.x;
    sm[t] = g_L[t] + g_L[t + 1024];
    __syncthreads();
    for (int st = 512; st > 0; st >>= 1) {
        if (t < st) sm[t] += sm[t + st];
        __syncthreads();
    }
    if (t == 0) out[0] = -sm[0] / (float)N_ROWS;
}

// ---------------------------------------------------------------------------
extern "C" void kernel_launch(void* const* d_in, const int* in_sizes, int n_in,
                              void* d_out, int out_size) {
    (void)in_sizes; (void)n_in; (void)out_size;
    const float* x     = (const float*)d_in[0];
    const float* W     = (const float*)d_in[1];
    const void*  label = d_in[2];
    float* out = (float*)d_out;

    cudaFuncSetAttribute(gemm_lse_mma, cudaFuncAttributeMaxDynamicSharedMemorySize, SMEM_TOTAL);

    detect_label_kernel<<<1, 256>>>((const int*)label);
    convertW_kernel<<<(CPAD * 12 + 255) / 256, 256>>>(W);
    norm_tgt_kernel<<<N_ROWS / 8, 256>>>(x, W, label);

    dim3 grid(STRIPES, N_ROWS / 128);
    gemm_lse_mma<<<grid, 256, SMEM_TOTAL>>>();

    combine_kernel<<<N_ROWS / 8, 256>>>();
    final_kernel<<<1, 1024>>>(out);
}